// round 1
// baseline (speedup 1.0000x reference)
#include <cuda_runtime.h>

#define BATCH 2048
#define TLEN  200
#define HD    128
#define NA0   64
#define NA1   16
#define TT    8
#define NB    16
#define RBLK  (BATCH / NB)   // 128 blocks

// Attention scores scratch (1.64 MB) — __device__ global (no allocs allowed)
__device__ float g_att[BATCH * TLEN];

// ---------- packed f32x2 helpers (FFMA2: 2x fp32 FMA throughput on sm_103a) ----------
__device__ __forceinline__ unsigned long long ffma2(unsigned long long a,
                                                    unsigned long long b,
                                                    unsigned long long c) {
    unsigned long long d;
    asm("fma.rn.f32x2 %0, %1, %2, %3;" : "=l"(d) : "l"(a), "l"(b), "l"(c));
    return d;
}
__device__ __forceinline__ float2 unpk(unsigned long long v) {
    float2 f;
    asm("mov.b64 {%0, %1}, %2;" : "=f"(f.x), "=f"(f.y) : "l"(v));
    return f;
}
__device__ __forceinline__ float sigm(float x) { return 1.0f / (1.0f + __expf(-x)); }

// ============================================================================
// Kernel 1: DIN attention MLP.  One block per batch element.
// Algebra: concat([q,k,q-k,q*k]) @ W0^T  ==  qpart[o] + sum_j Wk[o,j] * k[j]
//   qpart[o] = b0[o] + sum_j (W0a[o,j] + W0c[o,j]) q[j]
//   Wk[o,j]  = W0b[o,j] - W0c[o,j] + W0d[o,j]*q[j]
// ============================================================================
__global__ void __launch_bounds__(256) attn_kernel(
    const float* __restrict__ query, const float* __restrict__ keys,
    const float* __restrict__ W0, const float* __restrict__ b0,
    const float* __restrict__ W1, const float* __restrict__ b1,
    const float* __restrict__ Wd, const float* __restrict__ bd,
    const int* __restrict__ klen)
{
    __shared__ float sq[HD];
    __shared__ float sWk[NA0 * 132];   // pitch 132 floats: LDS.128 conflict-free
    __shared__ float sqp[NA0];
    __shared__ float skey[TT * 132];
    __shared__ float sa0[TT * 68];
    __shared__ float sa1[TT * NA1];
    __shared__ float sW1[NA1 * NA0];
    __shared__ float sWd[NA1];
    __shared__ float sb1[NA1];

    const int b    = blockIdx.x;
    const int tid  = threadIdx.x;
    const int lenb = klen[b];

    if (tid < HD) sq[tid] = query[b * HD + tid];
    if (tid < NA1) { sWd[tid] = Wd[tid]; sb1[tid] = b1[tid]; }
    for (int i = tid; i < NA1 * NA0; i += 256) sW1[i] = W1[i];
    __syncthreads();

    // qpart (64 small dots, one-time per block)
    if (tid < NA0) {
        const int o = tid;
        const float* w = W0 + o * (4 * HD);
        float s = b0[o];
        #pragma unroll 4
        for (int j = 0; j < HD; j++) s += (w[j] + w[2 * HD + j]) * sq[j];
        sqp[o] = s;
    }
    // Effective per-batch key weights
    for (int idx = tid; idx < NA0 * HD; idx += 256) {
        const int o = idx >> 7, j = idx & 127;
        const float* w = W0 + o * (4 * HD);
        sWk[o * 132 + j] = w[HD + j] - w[2 * HD + j] + w[3 * HD + j] * sq[j];
    }
    __syncthreads();

    const int warp = tid >> 5, lane = tid & 31;

    for (int t0 = 0; t0 < TLEN; t0 += TT) {
        if (t0 >= lenb) {                       // block-uniform branch
            if (tid < TT) g_att[b * TLEN + t0 + tid] = 0.0f;
            continue;
        }
        for (int idx = tid; idx < TT * HD; idx += 256) {
            const int tt = idx >> 7, j = idx & 127;
            skey[tt * 132 + j] = keys[(b * TLEN + t0 + tt) * HD + j];
        }
        __syncthreads();

        // layer 0: warp 'warp' handles t = t0+warp; lane computes o=lane, lane+32
        {
            unsigned long long acc0a = 0ull, acc0b = 0ull, acc1a = 0ull, acc1b = 0ull;
            const ulonglong2* kp  = reinterpret_cast<const ulonglong2*>(&skey[warp * 132]);
            const ulonglong2* w0p = reinterpret_cast<const ulonglong2*>(&sWk[lane * 132]);
            const ulonglong2* w1p = reinterpret_cast<const ulonglong2*>(&sWk[(lane + 32) * 132]);
            #pragma unroll 8
            for (int jc = 0; jc < HD / 4; jc++) {
                ulonglong2 x  = kp[jc];     // broadcast
                ulonglong2 wa = w0p[jc];
                ulonglong2 wb = w1p[jc];
                acc0a = ffma2(wa.x, x.x, acc0a);
                acc0b = ffma2(wa.y, x.y, acc0b);
                acc1a = ffma2(wb.x, x.x, acc1a);
                acc1b = ffma2(wb.y, x.y, acc1b);
            }
            float2 p = unpk(acc0a), q2 = unpk(acc0b);
            const float s0 = p.x + p.y + q2.x + q2.y + sqp[lane];
            p = unpk(acc1a); q2 = unpk(acc1b);
            const float s1 = p.x + p.y + q2.x + q2.y + sqp[lane + 32];
            sa0[warp * 68 + lane]      = sigm(s0);
            sa0[warp * 68 + lane + 32] = sigm(s1);
        }
        __syncthreads();

        // layer 1 (64 -> 16)
        if (tid < TT * NA1) {
            const int tt = tid >> 4, p = tid & 15;
            float s = sb1[p];
            #pragma unroll 8
            for (int o = 0; o < NA0; o++) s += sW1[p * NA0 + o] * sa0[tt * 68 + o];
            sa1[tt * NA1 + p] = sigm(s);
        }
        __syncthreads();

        // score (16 -> 1) + length mask
        if (tid < TT) {
            float s = bd[0];
            #pragma unroll
            for (int p = 0; p < NA1; p++) s += sWd[p] * sa1[tid * NA1 + p];
            g_att[b * TLEN + t0 + tid] = (t0 + tid < lenb) ? s : 0.0f;
        }
        __syncthreads();
    }
}

// ============================================================================
// Kernel 2: fused AUGRU scan.  One block owns NB=16 batches, loops t locally
// (no cross-block dependency: recurrence is independent per batch).
// Per step, thread r (0..383) computes gate row r for all 16 batches:
//   pass 1: bih[r] + Wih[r,:] . k_b   -> g1
//   pass 2: bhh[r] + Whh[r,:] . h_b   -> g2
// then 16x128 threads apply the gated update to h (kept in shared).
// ============================================================================
__global__ void __launch_bounds__(384, 1) rec_kernel(
    const float* __restrict__ keys,
    const float* __restrict__ Wih, const float* __restrict__ Whh,
    const float* __restrict__ bih, const float* __restrict__ bhh,
    const int* __restrict__ klen,
    float* __restrict__ out)
{
    extern __shared__ float sm[];
    float* sk   = sm;                     // NB*HD   (2048)
    float* sh   = sm + NB * HD;           // NB*HD   (2048)
    float* g1   = sm + 2 * NB * HD;       // NB*384  (6144)
    float* g2   = g1 + NB * 3 * HD;       // NB*384  (6144)
    float* satt = g2 + NB * 3 * HD;       // NB
    int*   slen = (int*)(satt + NB);      // NB
    __shared__ int smax;

    const int tid = threadIdx.x;
    const int b0  = blockIdx.x * NB;
    const int r   = tid;                  // gate row 0..383

    if (tid < NB) slen[tid] = klen[b0 + tid];
    for (int i = tid; i < NB * HD; i += 384) sh[i] = 0.0f;
    __syncthreads();
    if (tid == 0) {
        int m = 0;
        for (int b = 0; b < NB; b++) m = max(m, slen[b]);
        smax = m;
    }
    __syncthreads();
    const int tmax = smax;

    const float mybih = bih[r];
    const float mybhh = bhh[r];
    const ulonglong2* wihp = reinterpret_cast<const ulonglong2*>(Wih + r * HD);
    const ulonglong2* whhp = reinterpret_cast<const ulonglong2*>(Whh + r * HD);

    for (int t = 0; t < tmax; t++) {
        for (int i = tid; i < NB * HD; i += 384) {
            const int bb = i >> 7, j = i & 127;
            sk[i] = keys[((b0 + bb) * TLEN + t) * HD + j];
        }
        if (tid < NB) satt[tid] = g_att[(b0 + tid) * TLEN + t];
        __syncthreads();

        // pass 1: input transform  g1 = Wih . k + bih
        {
            unsigned long long acc[NB];
            #pragma unroll
            for (int b = 0; b < NB; b++) acc[b] = 0ull;
            #pragma unroll 4
            for (int jc = 0; jc < HD / 4; jc++) {
                const ulonglong2 w = wihp[jc];          // LDG.128 (L2-resident)
                #pragma unroll
                for (int b = 0; b < NB; b++) {
                    const ulonglong2 x =
                        *reinterpret_cast<const ulonglong2*>(&sk[b * HD + jc * 4]); // broadcast
                    acc[b] = ffma2(w.x, x.x, acc[b]);
                    acc[b] = ffma2(w.y, x.y, acc[b]);
                }
            }
            #pragma unroll
            for (int b = 0; b < NB; b++) {
                const float2 p = unpk(acc[b]);
                g1[b * 384 + r] = p.x + p.y + mybih;
            }
        }
        // pass 2: hidden transform  g2 = Whh . h + bhh
        {
            unsigned long long acc[NB];
            #pragma unroll
            for (int b = 0; b < NB; b++) acc[b] = 0ull;
            #pragma unroll 4
            for (int jc = 0; jc < HD / 4; jc++) {
                const ulonglong2 w = whhp[jc];
                #pragma unroll
                for (int b = 0; b < NB; b++) {
                    const ulonglong2 x =
                        *reinterpret_cast<const ulonglong2*>(&sh[b * HD + jc * 4]);
                    acc[b] = ffma2(w.x, x.x, acc[b]);
                    acc[b] = ffma2(w.y, x.y, acc[b]);
                }
            }
            #pragma unroll
            for (int b = 0; b < NB; b++) {
                const float2 p = unpk(acc[b]);
                g2[b * 384 + r] = p.x + p.y + mybhh;
            }
        }
        __syncthreads();

        // gated update (freeze past sequence end)
        for (int i = tid; i < NB * HD; i += 384) {
            const int bb = i >> 7, j = i & 127;
            if (t < slen[bb]) {
                const float rr = sigm(g1[bb * 384 + j]       + g2[bb * 384 + j]);
                const float zz = sigm(g1[bb * 384 + 128 + j] + g2[bb * 384 + 128 + j]) * satt[bb];
                const float nn = tanhf(g1[bb * 384 + 256 + j] + rr * g2[bb * 384 + 256 + j]);
                const float hp = sh[i];
                sh[i] = (1.0f - zz) * hp + zz * nn;
            }
        }
        __syncthreads();
    }

    for (int i = tid; i < NB * HD; i += 384) {
        const int bb = i >> 7, j = i & 127;
        out[(b0 + bb) * HD + j] = (slen[bb] > 0) ? sh[i] : 0.0f;
    }
}

// ============================================================================
extern "C" void kernel_launch(void* const* d_in, const int* in_sizes, int n_in,
                              void* d_out, int out_size)
{
    const float* query = (const float*)d_in[0];
    const float* keys  = (const float*)d_in[1];
    const float* W0    = (const float*)d_in[2];
    const float* b0    = (const float*)d_in[3];
    const float* W1    = (const float*)d_in[4];
    const float* b1    = (const float*)d_in[5];
    const float* Wd    = (const float*)d_in[6];
    const float* bd    = (const float*)d_in[7];
    const float* Wih   = (const float*)d_in[8];
    const float* Whh   = (const float*)d_in[9];
    const float* bih   = (const float*)d_in[10];
    const float* bhh   = (const float*)d_in[11];
    const int*   klen  = (const int*)d_in[12];
    float* out = (float*)d_out;

    const int rec_smem = (2 * NB * HD + 2 * NB * 3 * HD + NB) * (int)sizeof(float)
                         + NB * (int)sizeof(int);
    cudaFuncSetAttribute(rec_kernel, cudaFuncAttributeMaxDynamicSharedMemorySize, rec_smem);

    attn_kernel<<<BATCH, 256>>>(query, keys, W0, b0, W1, b1, Wd, bd, klen);
    rec_kernel<<<RBLK, 384, rec_smem>>>(keys, Wih, Whh, bih, bhh, klen, out);
}

// round 3
// speedup vs baseline: 2.6198x; 2.6198x over previous
#include <cuda_runtime.h>

#define BATCH 2048
#define TLEN  200
#define HD    128
#define NA0   64
#define NA1   16
#define TT    8
#define NB    16
#define RBLK  (BATCH / NB)   // 128 scan blocks
#define NR    384            // 3*HD gate rows

// ---------------- device scratch (no allocs allowed) ----------------
__device__ float g_att[BATCH * TLEN];            // 1.6 MB attention scores
__device__ float g_qp [BATCH * NA0];             // 0.5 MB qpart
__device__ float g_gi [BATCH * TLEN * NR];       // 629 MB  gi = keys@Wih^T + bih

// ---------------- packed f32x2 helpers ----------------
__device__ __forceinline__ unsigned long long ffma2(unsigned long long a,
                                                    unsigned long long b,
                                                    unsigned long long c) {
    unsigned long long d;
    asm("fma.rn.f32x2 %0, %1, %2, %3;" : "=l"(d) : "l"(a), "l"(b), "l"(c));
    return d;
}
__device__ __forceinline__ unsigned long long dup2(float x) {
    unsigned long long d;
    asm("mov.b64 %0, {%1, %1};" : "=l"(d) : "f"(x));
    return d;
}
__device__ __forceinline__ unsigned long long pack2(float x, float y) {
    unsigned long long d;
    asm("mov.b64 %0, {%1, %2};" : "=l"(d) : "f"(x), "f"(y));
    return d;
}
__device__ __forceinline__ float2 unpk(unsigned long long v) {
    float2 f;
    asm("mov.b64 {%0, %1}, %2;" : "=f"(f.x), "=f"(f.y) : "l"(v));
    return f;
}
__device__ __forceinline__ float sigm(float x) {
    return __fdividef(1.0f, 1.0f + __expf(-x));
}
__device__ __forceinline__ float tanh_fast(float x) {
    float y;
    asm("tanh.approx.f32 %0, %1;" : "=f"(y) : "f"(x));
    return y;
}

// ============================================================================
// Kernel 0: qpart[b][o] = b0[o] + sum_j (W0a[o,j]+W0c[o,j]) * q[b][j]
// ============================================================================
__global__ void __launch_bounds__(256) qpart_kernel(
    const float* __restrict__ query, const float* __restrict__ W0,
    const float* __restrict__ b0)
{
    __shared__ float sWeff[NA0 * 132];
    __shared__ float sqq[NB * HD];

    const int tid = threadIdx.x;
    const int b0i = blockIdx.x * NB;

    for (int idx = tid; idx < NA0 * HD; idx += 256) {
        const int o = idx >> 7, j = idx & 127;
        sWeff[o * 132 + j] = W0[o * (4 * HD) + j] + W0[o * (4 * HD) + 2 * HD + j];
    }
    for (int idx = tid; idx < NB * HD; idx += 256)
        sqq[idx] = query[b0i * HD + idx];
    __syncthreads();

    const int o  = tid & 63;
    const int bg = tid >> 6;           // 4 groups of 4 batches
    unsigned long long acc[4];
    #pragma unroll
    for (int i = 0; i < 4; i++) acc[i] = 0ull;

    #pragma unroll 4
    for (int jc = 0; jc < HD / 4; jc++) {
        const ulonglong2 w = *reinterpret_cast<const ulonglong2*>(&sWeff[o * 132 + jc * 4]);
        #pragma unroll
        for (int i = 0; i < 4; i++) {
            const ulonglong2 x =
                *reinterpret_cast<const ulonglong2*>(&sqq[(bg * 4 + i) * HD + jc * 4]);
            acc[i] = ffma2(w.x, x.x, acc[i]);
            acc[i] = ffma2(w.y, x.y, acc[i]);
        }
    }
    const float bo = b0[o];
    #pragma unroll
    for (int i = 0; i < 4; i++) {
        const float2 p = unpk(acc[i]);
        g_qp[(b0i + bg * 4 + i) * NA0 + o] = p.x + p.y + bo;
    }
}

// ============================================================================
// Kernel 1: DIN attention MLP (one block per batch).
// concat([q,k,q-k,q*k]) @ W0^T  ==  qpart[o] + sum_j Wk[o,j] * k[j]
// ============================================================================
__global__ void __launch_bounds__(256) attn_kernel(
    const float* __restrict__ query, const float* __restrict__ keys,
    const float* __restrict__ W0,
    const float* __restrict__ W1, const float* __restrict__ b1,
    const float* __restrict__ Wd, const float* __restrict__ bd,
    const int* __restrict__ klen)
{
    __shared__ float sq[HD];
    __shared__ float sWk[NA0 * 132];
    __shared__ float sqp[NA0];
    __shared__ float skey[TT * 132];
    __shared__ float sa0[TT * 68];
    __shared__ float sa1[TT * NA1];
    __shared__ float sW1[NA1 * NA0];
    __shared__ float sWd[NA1];
    __shared__ float sb1[NA1];

    const int b    = blockIdx.x;
    const int tid  = threadIdx.x;
    const int lenb = klen[b];

    if (tid < HD) sq[tid] = query[b * HD + tid];
    if (tid < NA1) { sWd[tid] = Wd[tid]; sb1[tid] = b1[tid]; }
    if (tid < NA0) sqp[tid] = g_qp[b * NA0 + tid];
    for (int i = tid; i < NA1 * NA0; i += 256) sW1[i] = W1[i];
    __syncthreads();

    for (int idx = tid; idx < NA0 * HD; idx += 256) {
        const int o = idx >> 7, j = idx & 127;
        const float* w = W0 + o * (4 * HD);
        sWk[o * 132 + j] = w[HD + j] - w[2 * HD + j] + w[3 * HD + j] * sq[j];
    }
    __syncthreads();

    const int warp = tid >> 5, lane = tid & 31;

    for (int t0 = 0; t0 < TLEN; t0 += TT) {
        if (t0 >= lenb) {
            if (tid < TT) g_att[b * TLEN + t0 + tid] = 0.0f;
            continue;
        }
        for (int idx = tid; idx < TT * HD; idx += 256) {
            const int tt = idx >> 7, j = idx & 127;
            skey[tt * 132 + j] = keys[(b * TLEN + t0 + tt) * HD + j];
        }
        __syncthreads();

        {
            unsigned long long acc0a = 0ull, acc0b = 0ull, acc1a = 0ull, acc1b = 0ull;
            const ulonglong2* kp  = reinterpret_cast<const ulonglong2*>(&skey[warp * 132]);
            const ulonglong2* w0p = reinterpret_cast<const ulonglong2*>(&sWk[lane * 132]);
            const ulonglong2* w1p = reinterpret_cast<const ulonglong2*>(&sWk[(lane + 32) * 132]);
            #pragma unroll 8
            for (int jc = 0; jc < HD / 4; jc++) {
                ulonglong2 x  = kp[jc];
                ulonglong2 wa = w0p[jc];
                ulonglong2 wb = w1p[jc];
                acc0a = ffma2(wa.x, x.x, acc0a);
                acc0b = ffma2(wa.y, x.y, acc0b);
                acc1a = ffma2(wb.x, x.x, acc1a);
                acc1b = ffma2(wb.y, x.y, acc1b);
            }
            float2 p = unpk(acc0a), q2 = unpk(acc0b);
            const float s0 = p.x + p.y + q2.x + q2.y + sqp[lane];
            p = unpk(acc1a); q2 = unpk(acc1b);
            const float s1 = p.x + p.y + q2.x + q2.y + sqp[lane + 32];
            sa0[warp * 68 + lane]      = sigm(s0);
            sa0[warp * 68 + lane + 32] = sigm(s1);
        }
        __syncthreads();

        if (tid < TT * NA1) {
            const int tt = tid >> 4, p = tid & 15;
            float s = sb1[p];
            #pragma unroll 8
            for (int o = 0; o < NA0; o++) s += sW1[p * NA0 + o] * sa0[tt * 68 + o];
            sa1[tt * NA1 + p] = sigm(s);
        }
        __syncthreads();

        if (tid < TT) {
            float s = bd[0];
            #pragma unroll
            for (int p = 0; p < NA1; p++) s += sWd[p] * sa1[tid * NA1 + p];
            g_att[b * TLEN + t0 + tid] = (t0 + tid < lenb) ? s : 0.0f;
        }
        __syncthreads();
    }
}

// ============================================================================
// Kernel 2: gi GEMM.  g_gi[b][t][r] = keys[b][t][:] . Wih[r][:] + bih[r]
// grid = (4 t-tiles of 64, 3 r-tiles of 128, 2048 batches); skips t-tiles
// past keys_length.  Thread tile 8t x 4r, f32x2 accumulators.
// ============================================================================
#define GI_SMEM ((64 * 132 + 128 * 132) * 4)

__global__ void __launch_bounds__(256) gi_kernel(
    const float* __restrict__ keys, const float* __restrict__ Wih,
    const float* __restrict__ bih, const int* __restrict__ klen)
{
    extern __shared__ float gsm[];
    float* sA  = gsm;               // [64][132]  keys tile (t-major)
    float* sBt = gsm + 64 * 132;    // [128][132] Wih^T tile (j-major)

    const int b   = blockIdx.z;
    const int t0  = blockIdx.x * 64;
    const int r0c = blockIdx.y * 128;
    if (t0 >= klen[b]) return;

    const int tid = threadIdx.x;

    for (int idx = tid; idx < 64 * HD; idx += 256) {
        const int tt = idx >> 7, j = idx & 127;
        const int tg = t0 + tt;
        sA[tt * 132 + j] = (tg < TLEN) ? keys[(b * TLEN + tg) * HD + j] : 0.0f;
    }
    for (int idx = tid; idx < 128 * HD; idx += 256) {
        const int rr = idx >> 7, j = idx & 127;
        sBt[j * 132 + rr] = Wih[(r0c + rr) * HD + j];
    }
    __syncthreads();

    const int rq = tid & 31;        // 32 r-quads -> 128 r
    const int tg = tid >> 5;        // 8 t-groups of 8
    const int rl = rq * 4;
    const int tl = tg * 8;

    unsigned long long accL[8], accH[8];
    #pragma unroll
    for (int i = 0; i < 8; i++) { accL[i] = 0ull; accH[i] = 0ull; }

    #pragma unroll 2
    for (int jc = 0; jc < HD / 4; jc++) {
        float4 a[8];
        #pragma unroll
        for (int tt = 0; tt < 8; tt++)
            a[tt] = *reinterpret_cast<const float4*>(&sA[(tl + tt) * 132 + jc * 4]);
        #pragma unroll
        for (int jj = 0; jj < 4; jj++) {
            const ulonglong2 w =
                *reinterpret_cast<const ulonglong2*>(&sBt[(jc * 4 + jj) * 132 + rl]);
            #pragma unroll
            for (int tt = 0; tt < 8; tt++) {
                const float av = (jj == 0) ? a[tt].x : (jj == 1) ? a[tt].y
                               : (jj == 2) ? a[tt].z : a[tt].w;
                const unsigned long long d = dup2(av);
                accL[tt] = ffma2(w.x, d, accL[tt]);
                accH[tt] = ffma2(w.y, d, accH[tt]);
            }
        }
    }

    const float4 bv = *reinterpret_cast<const float4*>(&bih[r0c + rl]);
    #pragma unroll
    for (int tt = 0; tt < 8; tt++) {
        const int tgl = t0 + tl + tt;
        if (tgl < TLEN) {
            const float2 lo = unpk(accL[tt]);
            const float2 hi = unpk(accH[tt]);
            float4 outv = make_float4(lo.x + bv.x, lo.y + bv.y, hi.x + bv.z, hi.y + bv.w);
            *reinterpret_cast<float4*>(&g_gi[(b * TLEN + tgl) * NR + r0c + rl]) = outv;
        }
    }
}

// ============================================================================
// Kernel 3: AUGRU scan.  Whh^T resident in shared (192KB).  One block = 16
// batches.  Per step: register-tiled [16x128]@[128x384] f32x2 GEMM for the
// hidden transform, then gated update.  gi prefetched into registers.
// ============================================================================
#define REC_SMEM ((HD * NR + NB * HD + NB * NR + NB) * 4 + NB * 4)

__global__ void __launch_bounds__(384, 1) rec_kernel(
    const float* __restrict__ Whh, const float* __restrict__ bhh,
    const int* __restrict__ klen, float* __restrict__ out)
{
    extern __shared__ float sm[];
    float* sWt  = sm;                       // [128][384]  Whh^T
    float* sh   = sm + HD * NR;             // [16][128]   hidden state
    float* sg2  = sh + NB * HD;             // [16][384]   Whh.h + bhh
    float* satt = sg2 + NB * NR;            // [16]
    int*   slen = (int*)(satt + NB);        // [16]
    __shared__ int smax;

    const int tid = threadIdx.x;
    const int b0  = blockIdx.x * NB;

    for (int idx = tid; idx < NR * HD; idx += 384) {
        const int r = idx >> 7, j = idx & 127;
        sWt[j * NR + r] = Whh[idx];
    }
    if (tid < NB) slen[tid] = klen[b0 + tid];
    for (int i = tid; i < NB * HD; i += 384) sh[i] = 0.0f;
    __syncthreads();
    if (tid == 0) {
        int m = 0;
        #pragma unroll
        for (int b = 0; b < NB; b++) m = max(m, slen[b]);
        smax = m;
    }
    __syncthreads();
    const int tmax = smax;

    // GEMM thread mapping: 4 batch-quads x 96 r-quads
    const int bq = tid / 96;
    const int rq = tid - bq * 96;
    const int rl = rq * 4;
    const int bl = bq * 4;
    const float4 bh = *reinterpret_cast<const float4*>(&bhh[rl]);
    const unsigned long long biasL = pack2(bh.x, bh.y);
    const unsigned long long biasH = pack2(bh.z, bh.w);

    for (int t = 0; t < tmax; t++) {
        // ---- prefetch gi (bih folded in) and att for this step ----
        float pr[6], pz[6], pn[6];
        #pragma unroll
        for (int k = 0; k < 6; k++) {
            const int i = tid + k * 384;
            if (i < NB * HD) {
                const int bb = i >> 7, j = i & 127;
                const float* g = &g_gi[((b0 + bb) * TLEN + t) * NR + j];
                pr[k] = g[0];
                pz[k] = g[HD];
                pn[k] = g[2 * HD];
            }
        }
        if (tid < NB) satt[tid] = g_att[(b0 + tid) * TLEN + t];

        // ---- hidden GEMM: sg2 = h @ Whh^T + bhh ----
        unsigned long long accL[4], accH[4];
        #pragma unroll
        for (int i = 0; i < 4; i++) { accL[i] = biasL; accH[i] = biasH; }

        #pragma unroll 4
        for (int jc = 0; jc < HD / 4; jc++) {
            float4 x[4];
            #pragma unroll
            for (int i = 0; i < 4; i++)
                x[i] = *reinterpret_cast<const float4*>(&sh[(bl + i) * HD + jc * 4]);
            #pragma unroll
            for (int jj = 0; jj < 4; jj++) {
                const ulonglong2 w =
                    *reinterpret_cast<const ulonglong2*>(&sWt[(jc * 4 + jj) * NR + rl]);
                #pragma unroll
                for (int i = 0; i < 4; i++) {
                    const float xv = (jj == 0) ? x[i].x : (jj == 1) ? x[i].y
                                   : (jj == 2) ? x[i].z : x[i].w;
                    const unsigned long long d = dup2(xv);
                    accL[i] = ffma2(w.x, d, accL[i]);
                    accH[i] = ffma2(w.y, d, accH[i]);
                }
            }
        }
        #pragma unroll
        for (int i = 0; i < 4; i++) {
            ulonglong2 v; v.x = accL[i]; v.y = accH[i];
            *reinterpret_cast<ulonglong2*>(&sg2[(bl + i) * NR + rl]) = v;
        }
        __syncthreads();

        // ---- gated update (freeze past sequence end) ----
        #pragma unroll
        for (int k = 0; k < 6; k++) {
            const int i = tid + k * 384;
            if (i < NB * HD) {
                const int bb = i >> 7, j = i & 127;
                if (t < slen[bb]) {
                    const float g2r = sg2[bb * NR + j];
                    const float g2z = sg2[bb * NR + HD + j];
                    const float g2n = sg2[bb * NR + 2 * HD + j];
                    const float rr = sigm(pr[k] + g2r);
                    const float zz = sigm(pz[k] + g2z) * satt[bb];
                    const float nn = tanh_fast(pn[k] + rr * g2n);
                    sh[i] = (1.0f - zz) * sh[i] + zz * nn;
                }
            }
        }
        __syncthreads();
    }

    for (int i = tid; i < NB * HD; i += 384) {
        const int bb = i >> 7, j = i & 127;
        out[(b0 + bb) * HD + j] = (slen[bb] > 0) ? sh[i] : 0.0f;
    }
}

// ============================================================================
extern "C" void kernel_launch(void* const* d_in, const int* in_sizes, int n_in,
                              void* d_out, int out_size)
{
    const float* query = (const float*)d_in[0];
    const float* keys  = (const float*)d_in[1];
    const float* W0    = (const float*)d_in[2];
    const float* b0    = (const float*)d_in[3];
    const float* W1    = (const float*)d_in[4];
    const float* b1    = (const float*)d_in[5];
    const float* Wd    = (const float*)d_in[6];
    const float* bd    = (const float*)d_in[7];
    const float* Wih   = (const float*)d_in[8];
    const float* Whh   = (const float*)d_in[9];
    const float* bih   = (const float*)d_in[10];
    const float* bhh   = (const float*)d_in[11];
    const int*   klen  = (const int*)d_in[12];
    float* out = (float*)d_out;

    cudaFuncSetAttribute(gi_kernel,  cudaFuncAttributeMaxDynamicSharedMemorySize, GI_SMEM);
    cudaFuncSetAttribute(rec_kernel, cudaFuncAttributeMaxDynamicSharedMemorySize, REC_SMEM);

    qpart_kernel<<<BATCH / NB, 256>>>(query, W0, b0);
    attn_kernel<<<BATCH, 256>>>(query, keys, W0, W1, b1, Wd, bd, klen);
    gi_kernel<<<dim3(4, 3, BATCH), 256, GI_SMEM>>>(keys, Wih, bih, klen);
    rec_kernel<<<RBLK, 384, REC_SMEM>>>(Whh, bhh, klen, out);
}

// round 4
// speedup vs baseline: 2.6232x; 1.0013x over previous
#include <cuda_runtime.h>

#define BATCH 2048
#define TLEN  200
#define HD    128
#define NA0   64
#define NA1   16
#define TT    8
#define NB    16
#define RBLK  (BATCH / NB)   // 128 scan blocks
#define NR    384            // 3*HD gate rows
#define SHP   132            // sh pitch (floats): bank-shift 16 per batch-quad
#define SG2P  388            // sg2 pitch (floats)

// ---------------- device scratch (no allocs allowed) ----------------
__device__ float g_att[BATCH * TLEN];            // 1.6 MB attention scores
__device__ float g_qp [BATCH * NA0];             // 0.5 MB qpart
__device__ float g_gi [BATCH * TLEN * NR];       // 629 MB  gi = keys@Wih^T + bih

// ---------------- packed f32x2 helpers ----------------
__device__ __forceinline__ unsigned long long ffma2(unsigned long long a,
                                                    unsigned long long b,
                                                    unsigned long long c) {
    unsigned long long d;
    asm("fma.rn.f32x2 %0, %1, %2, %3;" : "=l"(d) : "l"(a), "l"(b), "l"(c));
    return d;
}
__device__ __forceinline__ unsigned long long dup2(float x) {
    unsigned long long d;
    asm("mov.b64 %0, {%1, %1};" : "=l"(d) : "f"(x));
    return d;
}
__device__ __forceinline__ unsigned long long pack2(float x, float y) {
    unsigned long long d;
    asm("mov.b64 %0, {%1, %2};" : "=l"(d) : "f"(x), "f"(y));
    return d;
}
__device__ __forceinline__ float2 unpk(unsigned long long v) {
    float2 f;
    asm("mov.b64 {%0, %1}, %2;" : "=f"(f.x), "=f"(f.y) : "l"(v));
    return f;
}
__device__ __forceinline__ float sigm(float x) {
    return __fdividef(1.0f, 1.0f + __expf(-x));
}
__device__ __forceinline__ float tanh_fast(float x) {
    float y;
    asm("tanh.approx.f32 %0, %1;" : "=f"(y) : "f"(x));
    return y;
}

// ============================================================================
// Kernel 0: qpart[b][o] = b0[o] + sum_j (W0a[o,j]+W0c[o,j]) * q[b][j]
// ============================================================================
__global__ void __launch_bounds__(256) qpart_kernel(
    const float* __restrict__ query, const float* __restrict__ W0,
    const float* __restrict__ b0)
{
    __shared__ float sWeff[NA0 * 132];
    __shared__ float sqq[NB * HD];

    const int tid = threadIdx.x;
    const int b0i = blockIdx.x * NB;

    for (int idx = tid; idx < NA0 * HD; idx += 256) {
        const int o = idx >> 7, j = idx & 127;
        sWeff[o * 132 + j] = W0[o * (4 * HD) + j] + W0[o * (4 * HD) + 2 * HD + j];
    }
    for (int idx = tid; idx < NB * HD; idx += 256)
        sqq[idx] = query[b0i * HD + idx];
    __syncthreads();

    const int o  = tid & 63;
    const int bg = tid >> 6;
    unsigned long long acc[4];
    #pragma unroll
    for (int i = 0; i < 4; i++) acc[i] = 0ull;

    #pragma unroll 4
    for (int jc = 0; jc < HD / 4; jc++) {
        const ulonglong2 w = *reinterpret_cast<const ulonglong2*>(&sWeff[o * 132 + jc * 4]);
        #pragma unroll
        for (int i = 0; i < 4; i++) {
            const ulonglong2 x =
                *reinterpret_cast<const ulonglong2*>(&sqq[(bg * 4 + i) * HD + jc * 4]);
            acc[i] = ffma2(w.x, x.x, acc[i]);
            acc[i] = ffma2(w.y, x.y, acc[i]);
        }
    }
    const float bo = b0[o];
    #pragma unroll
    for (int i = 0; i < 4; i++) {
        const float2 p = unpk(acc[i]);
        g_qp[(b0i + bg * 4 + i) * NA0 + o] = p.x + p.y + bo;
    }
}

// ============================================================================
// Kernel 1: DIN attention MLP (one block per batch).
// ============================================================================
__global__ void __launch_bounds__(256) attn_kernel(
    const float* __restrict__ query, const float* __restrict__ keys,
    const float* __restrict__ W0,
    const float* __restrict__ W1, const float* __restrict__ b1,
    const float* __restrict__ Wd, const float* __restrict__ bd,
    const int* __restrict__ klen)
{
    __shared__ float sq[HD];
    __shared__ float sWk[NA0 * 132];
    __shared__ float sqp[NA0];
    __shared__ float skey[TT * 132];
    __shared__ float sa0[TT * 68];
    __shared__ float sa1[TT * NA1];
    __shared__ float sW1[NA1 * NA0];
    __shared__ float sWd[NA1];
    __shared__ float sb1[NA1];

    const int b    = blockIdx.x;
    const int tid  = threadIdx.x;
    const int lenb = klen[b];

    if (tid < HD) sq[tid] = query[b * HD + tid];
    if (tid < NA1) { sWd[tid] = Wd[tid]; sb1[tid] = b1[tid]; }
    if (tid < NA0) sqp[tid] = g_qp[b * NA0 + tid];
    for (int i = tid; i < NA1 * NA0; i += 256) sW1[i] = W1[i];
    __syncthreads();

    for (int idx = tid; idx < NA0 * HD; idx += 256) {
        const int o = idx >> 7, j = idx & 127;
        const float* w = W0 + o * (4 * HD);
        sWk[o * 132 + j] = w[HD + j] - w[2 * HD + j] + w[3 * HD + j] * sq[j];
    }
    __syncthreads();

    const int warp = tid >> 5, lane = tid & 31;

    for (int t0 = 0; t0 < TLEN; t0 += TT) {
        if (t0 >= lenb) {
            if (tid < TT) g_att[b * TLEN + t0 + tid] = 0.0f;
            continue;
        }
        for (int idx = tid; idx < TT * HD; idx += 256) {
            const int tt = idx >> 7, j = idx & 127;
            skey[tt * 132 + j] = keys[(b * TLEN + t0 + tt) * HD + j];
        }
        __syncthreads();

        {
            unsigned long long acc0a = 0ull, acc0b = 0ull, acc1a = 0ull, acc1b = 0ull;
            const ulonglong2* kp  = reinterpret_cast<const ulonglong2*>(&skey[warp * 132]);
            const ulonglong2* w0p = reinterpret_cast<const ulonglong2*>(&sWk[lane * 132]);
            const ulonglong2* w1p = reinterpret_cast<const ulonglong2*>(&sWk[(lane + 32) * 132]);
            #pragma unroll 8
            for (int jc = 0; jc < HD / 4; jc++) {
                ulonglong2 x  = kp[jc];
                ulonglong2 wa = w0p[jc];
                ulonglong2 wb = w1p[jc];
                acc0a = ffma2(wa.x, x.x, acc0a);
                acc0b = ffma2(wa.y, x.y, acc0b);
                acc1a = ffma2(wb.x, x.x, acc1a);
                acc1b = ffma2(wb.y, x.y, acc1b);
            }
            float2 p = unpk(acc0a), q2 = unpk(acc0b);
            const float s0 = p.x + p.y + q2.x + q2.y + sqp[lane];
            p = unpk(acc1a); q2 = unpk(acc1b);
            const float s1 = p.x + p.y + q2.x + q2.y + sqp[lane + 32];
            sa0[warp * 68 + lane]      = sigm(s0);
            sa0[warp * 68 + lane + 32] = sigm(s1);
        }
        __syncthreads();

        if (tid < TT * NA1) {
            const int tt = tid >> 4, p = tid & 15;
            float s = sb1[p];
            #pragma unroll 8
            for (int o = 0; o < NA0; o++) s += sW1[p * NA0 + o] * sa0[tt * 68 + o];
            sa1[tt * NA1 + p] = sigm(s);
        }
        __syncthreads();

        if (tid < TT) {
            float s = bd[0];
            #pragma unroll
            for (int p = 0; p < NA1; p++) s += sWd[p] * sa1[tid * NA1 + p];
            g_att[b * TLEN + t0 + tid] = (t0 + tid < lenb) ? s : 0.0f;
        }
        __syncthreads();
    }
}

// ============================================================================
// Kernel 2: gi GEMM.  g_gi[b][t][r] = keys[b][t][:] . Wih[r][:] + bih[r]
// ============================================================================
#define GI_SMEM ((64 * 132 + 128 * 132) * 4)

__global__ void __launch_bounds__(256) gi_kernel(
    const float* __restrict__ keys, const float* __restrict__ Wih,
    const float* __restrict__ bih, const int* __restrict__ klen)
{
    extern __shared__ float gsm[];
    float* sA  = gsm;               // [64][132]  keys tile (t-major)
    float* sBt = gsm + 64 * 132;    // [128][132] Wih^T tile (j-major)

    const int b   = blockIdx.z;
    const int t0  = blockIdx.x * 64;
    const int r0c = blockIdx.y * 128;
    if (t0 >= klen[b]) return;

    const int tid = threadIdx.x;

    for (int idx = tid; idx < 64 * HD; idx += 256) {
        const int tt = idx >> 7, j = idx & 127;
        const int tg = t0 + tt;
        sA[tt * 132 + j] = (tg < TLEN) ? keys[(b * TLEN + tg) * HD + j] : 0.0f;
    }
    for (int idx = tid; idx < 128 * HD; idx += 256) {
        const int rr = idx >> 7, j = idx & 127;
        sBt[j * 132 + rr] = Wih[(r0c + rr) * HD + j];
    }
    __syncthreads();

    const int rq = tid & 31;
    const int tg = tid >> 5;
    const int rl = rq * 4;
    const int tl = tg * 8;

    unsigned long long accL[8], accH[8];
    #pragma unroll
    for (int i = 0; i < 8; i++) { accL[i] = 0ull; accH[i] = 0ull; }

    #pragma unroll 2
    for (int jc = 0; jc < HD / 4; jc++) {
        float4 a[8];
        #pragma unroll
        for (int tt = 0; tt < 8; tt++)
            a[tt] = *reinterpret_cast<const float4*>(&sA[(tl + tt) * 132 + jc * 4]);
        #pragma unroll
        for (int jj = 0; jj < 4; jj++) {
            const ulonglong2 w =
                *reinterpret_cast<const ulonglong2*>(&sBt[(jc * 4 + jj) * 132 + rl]);
            #pragma unroll
            for (int tt = 0; tt < 8; tt++) {
                const float av = (jj == 0) ? a[tt].x : (jj == 1) ? a[tt].y
                               : (jj == 2) ? a[tt].z : a[tt].w;
                const unsigned long long d = dup2(av);
                accL[tt] = ffma2(w.x, d, accL[tt]);
                accH[tt] = ffma2(w.y, d, accH[tt]);
            }
        }
    }

    const float4 bv = *reinterpret_cast<const float4*>(&bih[r0c + rl]);
    #pragma unroll
    for (int tt = 0; tt < 8; tt++) {
        const int tgl = t0 + tl + tt;
        if (tgl < TLEN) {
            const float2 lo = unpk(accL[tt]);
            const float2 hi = unpk(accH[tt]);
            float4 outv = make_float4(lo.x + bv.x, lo.y + bv.y, hi.x + bv.z, hi.y + bv.w);
            *reinterpret_cast<float4*>(&g_gi[(b * TLEN + tgl) * NR + r0c + rl]) = outv;
        }
    }
}

// ============================================================================
// Kernel 3: AUGRU scan.  Whh^T resident in shared (192KB).  One block = 16
// batches.  Lane mapping: rql = lane&7 (8 r-quads/warp, 128B contiguous -> w
// LDS.128 is 1-phase), bq = lane>>3.  sh pitch 132 -> x loads 2-phase.
// ============================================================================
#define REC_SMEM ((HD * NR + NB * SHP + NB * SG2P + NB) * 4 + NB * 4)

__global__ void __launch_bounds__(384, 1) rec_kernel(
    const float* __restrict__ Whh, const float* __restrict__ bhh,
    const int* __restrict__ klen, float* __restrict__ out)
{
    extern __shared__ float sm[];
    float* sWt  = sm;                       // [128][384]  Whh^T
    float* sh   = sm + HD * NR;             // [16][SHP]   hidden state
    float* sg2  = sh + NB * SHP;            // [16][SG2P]  Whh.h + bhh
    float* satt = sg2 + NB * SG2P;          // [16]
    int*   slen = (int*)(satt + NB);        // [16]
    __shared__ int smax;

    const int tid = threadIdx.x;
    const int b0  = blockIdx.x * NB;

    for (int idx = tid; idx < NR * HD; idx += 384) {
        const int r = idx >> 7, j = idx & 127;
        sWt[j * NR + r] = Whh[idx];
    }
    if (tid < NB) slen[tid] = klen[b0 + tid];
    for (int i = tid; i < NB * SHP; i += 384) sh[i] = 0.0f;
    __syncthreads();
    if (tid == 0) {
        int m = 0;
        #pragma unroll
        for (int b = 0; b < NB; b++) m = max(m, slen[b]);
        smax = m;
    }
    __syncthreads();
    const int tmax = smax;

    // GEMM thread mapping: warp covers r-quads [warp*8, warp*8+8), lane&7
    // selects the quad (contiguous 128B -> 1-phase w load), lane>>3 = bq.
    const int lane = tid & 31, warp = tid >> 5;
    const int rl = (warp * 8 + (lane & 7)) * 4;
    const int bl = (lane >> 3) * 4;
    const float4 bh = *reinterpret_cast<const float4*>(&bhh[rl]);
    const unsigned long long biasL = pack2(bh.x, bh.y);
    const unsigned long long biasH = pack2(bh.z, bh.w);

    for (int t = 0; t < tmax; t++) {
        // ---- prefetch gi (bih folded in) and att for this step ----
        float pr[6], pz[6], pn[6];
        #pragma unroll
        for (int k = 0; k < 6; k++) {
            const int i = tid + k * 384;
            if (i < NB * HD) {
                const int bb = i >> 7, j = i & 127;
                const float* g = &g_gi[((b0 + bb) * TLEN + t) * NR + j];
                pr[k] = g[0];
                pz[k] = g[HD];
                pn[k] = g[2 * HD];
            }
        }
        if (tid < NB) satt[tid] = g_att[(b0 + tid) * TLEN + t];

        // ---- hidden GEMM: sg2 = h @ Whh^T + bhh ----
        unsigned long long accL[4], accH[4];
        #pragma unroll
        for (int i = 0; i < 4; i++) { accL[i] = biasL; accH[i] = biasH; }

        #pragma unroll 4
        for (int jc = 0; jc < HD / 4; jc++) {
            float4 x[4];
            #pragma unroll
            for (int i = 0; i < 4; i++)
                x[i] = *reinterpret_cast<const float4*>(&sh[(bl + i) * SHP + jc * 4]);
            #pragma unroll
            for (int jj = 0; jj < 4; jj++) {
                const ulonglong2 w =
                    *reinterpret_cast<const ulonglong2*>(&sWt[(jc * 4 + jj) * NR + rl]);
                #pragma unroll
                for (int i = 0; i < 4; i++) {
                    const float xv = (jj == 0) ? x[i].x : (jj == 1) ? x[i].y
                                   : (jj == 2) ? x[i].z : x[i].w;
                    const unsigned long long d = dup2(xv);
                    accL[i] = ffma2(w.x, d, accL[i]);
                    accH[i] = ffma2(w.y, d, accH[i]);
                }
            }
        }
        #pragma unroll
        for (int i = 0; i < 4; i++) {
            ulonglong2 v; v.x = accL[i]; v.y = accH[i];
            *reinterpret_cast<ulonglong2*>(&sg2[(bl + i) * SG2P + rl]) = v;
        }
        __syncthreads();

        // ---- gated update (freeze past sequence end) ----
        #pragma unroll
        for (int k = 0; k < 6; k++) {
            const int i = tid + k * 384;
            if (i < NB * HD) {
                const int bb = i >> 7, j = i & 127;
                if (t < slen[bb]) {
                    const float g2r = sg2[bb * SG2P + j];
                    const float g2z = sg2[bb * SG2P + HD + j];
                    const float g2n = sg2[bb * SG2P + 2 * HD + j];
                    const float rr = sigm(pr[k] + g2r);
                    const float zz = sigm(pz[k] + g2z) * satt[bb];
                    const float nn = tanh_fast(pn[k] + rr * g2n);
                    sh[bb * SHP + j] = (1.0f - zz) * sh[bb * SHP + j] + zz * nn;
                }
            }
        }
        __syncthreads();
    }

    for (int i = tid; i < NB * HD; i += 384) {
        const int bb = i >> 7, j = i & 127;
        out[(b0 + bb) * HD + j] = (slen[bb] > 0) ? sh[bb * SHP + j] : 0.0f;
    }
}

// ============================================================================
extern "C" void kernel_launch(void* const* d_in, const int* in_sizes, int n_in,
                              void* d_out, int out_size)
{
    const float* query = (const float*)d_in[0];
    const float* keys  = (const float*)d_in[1];
    const float* W0    = (const float*)d_in[2];
    const float* b0    = (const float*)d_in[3];
    const float* W1    = (const float*)d_in[4];
    const float* b1    = (const float*)d_in[5];
    const float* Wd    = (const float*)d_in[6];
    const float* bd    = (const float*)d_in[7];
    const float* Wih   = (const float*)d_in[8];
    const float* Whh   = (const float*)d_in[9];
    const float* bih   = (const float*)d_in[10];
    const float* bhh   = (const float*)d_in[11];
    const int*   klen  = (const int*)d_in[12];
    float* out = (float*)d_out;

    cudaFuncSetAttribute(gi_kernel,  cudaFuncAttributeMaxDynamicSharedMemorySize, GI_SMEM);
    cudaFuncSetAttribute(rec_kernel, cudaFuncAttributeMaxDynamicSharedMemorySize, REC_SMEM);

    qpart_kernel<<<BATCH / NB, 256>>>(query, W0, b0);
    attn_kernel<<<BATCH, 256>>>(query, keys, W0, W1, b1, Wd, bd, klen);
    gi_kernel<<<dim3(4, 3, BATCH), 256, GI_SMEM>>>(keys, Wih, bih, klen);
    rec_kernel<<<RBLK, 384, REC_SMEM>>>(Whh, bhh, klen, out);
}

// round 5
// speedup vs baseline: 2.6815x; 1.0222x over previous
#include <cuda_runtime.h>

#define BATCH 2048
#define TLEN  200
#define HD    128
#define NA0   64
#define NA1   16
#define TT    8
#define NB    16
#define RBLK  (BATCH / NB)   // 128 scan blocks
#define NR    384            // 3*HD gate rows
#define SHP   132            // sh pitch (floats)
#define SG2P  388            // sg2 pitch (floats)

// ---------------- device scratch (no allocs allowed) ----------------
__device__ float g_att[BATCH * TLEN];            // 1.6 MB attention scores
__device__ float g_qp [BATCH * NA0];             // 0.5 MB qpart
__device__ float g_gi [BATCH * TLEN * NR];       // 629 MB  gi = keys@Wih^T + bih

// ---------------- packed f32x2 helpers ----------------
__device__ __forceinline__ unsigned long long ffma2(unsigned long long a,
                                                    unsigned long long b,
                                                    unsigned long long c) {
    unsigned long long d;
    asm("fma.rn.f32x2 %0, %1, %2, %3;" : "=l"(d) : "l"(a), "l"(b), "l"(c));
    return d;
}
__device__ __forceinline__ unsigned long long dup2(float x) {
    unsigned long long d;
    asm("mov.b64 %0, {%1, %1};" : "=l"(d) : "f"(x));
    return d;
}
__device__ __forceinline__ float2 unpk(unsigned long long v) {
    float2 f;
    asm("mov.b64 {%0, %1}, %2;" : "=f"(f.x), "=f"(f.y) : "l"(v));
    return f;
}
__device__ __forceinline__ float sigm(float x) {
    return __fdividef(1.0f, 1.0f + __expf(-x));
}
__device__ __forceinline__ float tanh_fast(float x) {
    float y;
    asm("tanh.approx.f32 %0, %1;" : "=f"(y) : "f"(x));
    return y;
}
// sigmoid via single MUFU: 0.5*tanh(0.5x)+0.5
__device__ __forceinline__ float sigm_t(float x) {
    return fmaf(0.5f, tanh_fast(0.5f * x), 0.5f);
}

// ============================================================================
// Kernel 0: qpart[b][o] = b0[o] + sum_j (W0a[o,j]+W0c[o,j]) * q[b][j]
// ============================================================================
__global__ void __launch_bounds__(256) qpart_kernel(
    const float* __restrict__ query, const float* __restrict__ W0,
    const float* __restrict__ b0)
{
    __shared__ float sWeff[NA0 * 132];
    __shared__ float sqq[NB * HD];

    const int tid = threadIdx.x;
    const int b0i = blockIdx.x * NB;

    for (int idx = tid; idx < NA0 * HD; idx += 256) {
        const int o = idx >> 7, j = idx & 127;
        sWeff[o * 132 + j] = W0[o * (4 * HD) + j] + W0[o * (4 * HD) + 2 * HD + j];
    }
    for (int idx = tid; idx < NB * HD; idx += 256)
        sqq[idx] = query[b0i * HD + idx];
    __syncthreads();

    const int o  = tid & 63;
    const int bg = tid >> 6;
    unsigned long long acc[4];
    #pragma unroll
    for (int i = 0; i < 4; i++) acc[i] = 0ull;

    #pragma unroll 4
    for (int jc = 0; jc < HD / 4; jc++) {
        const ulonglong2 w = *reinterpret_cast<const ulonglong2*>(&sWeff[o * 132 + jc * 4]);
        #pragma unroll
        for (int i = 0; i < 4; i++) {
            const ulonglong2 x =
                *reinterpret_cast<const ulonglong2*>(&sqq[(bg * 4 + i) * HD + jc * 4]);
            acc[i] = ffma2(w.x, x.x, acc[i]);
            acc[i] = ffma2(w.y, x.y, acc[i]);
        }
    }
    const float bo = b0[o];
    #pragma unroll
    for (int i = 0; i < 4; i++) {
        const float2 p = unpk(acc[i]);
        g_qp[(b0i + bg * 4 + i) * NA0 + o] = p.x + p.y + bo;
    }
}

// ============================================================================
// Kernel 1: DIN attention MLP (one block per batch).
// ============================================================================
__global__ void __launch_bounds__(256) attn_kernel(
    const float* __restrict__ query, const float* __restrict__ keys,
    const float* __restrict__ W0,
    const float* __restrict__ W1, const float* __restrict__ b1,
    const float* __restrict__ Wd, const float* __restrict__ bd,
    const int* __restrict__ klen)
{
    __shared__ float sq[HD];
    __shared__ float sWk[NA0 * 132];
    __shared__ float sqp[NA0];
    __shared__ float skey[TT * 132];
    __shared__ float sa0[TT * 68];
    __shared__ float sa1[TT * NA1];
    __shared__ float sW1[NA1 * NA0];
    __shared__ float sWd[NA1];
    __shared__ float sb1[NA1];

    const int b    = blockIdx.x;
    const int tid  = threadIdx.x;
    const int lenb = klen[b];

    if (tid < HD) sq[tid] = query[b * HD + tid];
    if (tid < NA1) { sWd[tid] = Wd[tid]; sb1[tid] = b1[tid]; }
    if (tid < NA0) sqp[tid] = g_qp[b * NA0 + tid];
    for (int i = tid; i < NA1 * NA0; i += 256) sW1[i] = W1[i];
    __syncthreads();

    for (int idx = tid; idx < NA0 * HD; idx += 256) {
        const int o = idx >> 7, j = idx & 127;
        const float* w = W0 + o * (4 * HD);
        sWk[o * 132 + j] = w[HD + j] - w[2 * HD + j] + w[3 * HD + j] * sq[j];
    }
    __syncthreads();

    const int warp = tid >> 5, lane = tid & 31;

    for (int t0 = 0; t0 < TLEN; t0 += TT) {
        if (t0 >= lenb) {
            if (tid < TT) g_att[b * TLEN + t0 + tid] = 0.0f;
            continue;
        }
        for (int idx = tid; idx < TT * HD; idx += 256) {
            const int tt = idx >> 7, j = idx & 127;
            skey[tt * 132 + j] = keys[(b * TLEN + t0 + tt) * HD + j];
        }
        __syncthreads();

        {
            unsigned long long acc0a = 0ull, acc0b = 0ull, acc1a = 0ull, acc1b = 0ull;
            const ulonglong2* kp  = reinterpret_cast<const ulonglong2*>(&skey[warp * 132]);
            const ulonglong2* w0p = reinterpret_cast<const ulonglong2*>(&sWk[lane * 132]);
            const ulonglong2* w1p = reinterpret_cast<const ulonglong2*>(&sWk[(lane + 32) * 132]);
            #pragma unroll 8
            for (int jc = 0; jc < HD / 4; jc++) {
                ulonglong2 x  = kp[jc];
                ulonglong2 wa = w0p[jc];
                ulonglong2 wb = w1p[jc];
                acc0a = ffma2(wa.x, x.x, acc0a);
                acc0b = ffma2(wa.y, x.y, acc0b);
                acc1a = ffma2(wb.x, x.x, acc1a);
                acc1b = ffma2(wb.y, x.y, acc1b);
            }
            float2 p = unpk(acc0a), q2 = unpk(acc0b);
            const float s0 = p.x + p.y + q2.x + q2.y + sqp[lane];
            p = unpk(acc1a); q2 = unpk(acc1b);
            const float s1 = p.x + p.y + q2.x + q2.y + sqp[lane + 32];
            sa0[warp * 68 + lane]      = sigm(s0);
            sa0[warp * 68 + lane + 32] = sigm(s1);
        }
        __syncthreads();

        if (tid < TT * NA1) {
            const int tt = tid >> 4, p = tid & 15;
            float s = sb1[p];
            #pragma unroll 8
            for (int o = 0; o < NA0; o++) s += sW1[p * NA0 + o] * sa0[tt * 68 + o];
            sa1[tt * NA1 + p] = sigm(s);
        }
        __syncthreads();

        if (tid < TT) {
            float s = bd[0];
            #pragma unroll
            for (int p = 0; p < NA1; p++) s += sWd[p] * sa1[tid * NA1 + p];
            g_att[b * TLEN + t0 + tid] = (t0 + tid < lenb) ? s : 0.0f;
        }
        __syncthreads();
    }
}

// ============================================================================
// Kernel 2: gi GEMM.  g_gi[b][t][r] = keys[b][t][:] . Wih[r][:] + bih[r]
// Per-thread length skip: threads whose entire 8-row t-slab is past
// keys_length do no FMA work (tile-level skip stays too).
// ============================================================================
#define GI_SMEM ((64 * 132 + 128 * 132) * 4)

__global__ void __launch_bounds__(256) gi_kernel(
    const float* __restrict__ keys, const float* __restrict__ Wih,
    const float* __restrict__ bih, const int* __restrict__ klen)
{
    extern __shared__ float gsm[];
    float* sA  = gsm;               // [64][132]  keys tile (t-major)
    float* sBt = gsm + 64 * 132;    // [128][132] Wih^T tile (j-major)

    const int b   = blockIdx.z;
    const int t0  = blockIdx.x * 64;
    const int r0c = blockIdx.y * 128;
    const int lenb = klen[b];
    if (t0 >= lenb) return;

    const int tid = threadIdx.x;

    for (int idx = tid; idx < 64 * HD; idx += 256) {
        const int tt = idx >> 7, j = idx & 127;
        const int tg = t0 + tt;
        sA[tt * 132 + j] = (tg < TLEN) ? keys[(b * TLEN + tg) * HD + j] : 0.0f;
    }
    for (int idx = tid; idx < 128 * HD; idx += 256) {
        const int rr = idx >> 7, j = idx & 127;
        sBt[j * 132 + rr] = Wih[(r0c + rr) * HD + j];
    }
    __syncthreads();

    const int rq = tid & 31;
    const int tg = tid >> 5;
    const int rl = rq * 4;
    const int tl = tg * 8;

    if (t0 + tl >= lenb) return;   // whole 8-row slab past length: skip

    unsigned long long accL[8], accH[8];
    #pragma unroll
    for (int i = 0; i < 8; i++) { accL[i] = 0ull; accH[i] = 0ull; }

    #pragma unroll 2
    for (int jc = 0; jc < HD / 4; jc++) {
        float4 a[8];
        #pragma unroll
        for (int tt = 0; tt < 8; tt++)
            a[tt] = *reinterpret_cast<const float4*>(&sA[(tl + tt) * 132 + jc * 4]);
        #pragma unroll
        for (int jj = 0; jj < 4; jj++) {
            const ulonglong2 w =
                *reinterpret_cast<const ulonglong2*>(&sBt[(jc * 4 + jj) * 132 + rl]);
            #pragma unroll
            for (int tt = 0; tt < 8; tt++) {
                const float av = (jj == 0) ? a[tt].x : (jj == 1) ? a[tt].y
                               : (jj == 2) ? a[tt].z : a[tt].w;
                const unsigned long long d = dup2(av);
                accL[tt] = ffma2(w.x, d, accL[tt]);
                accH[tt] = ffma2(w.y, d, accH[tt]);
            }
        }
    }

    const float4 bv = *reinterpret_cast<const float4*>(&bih[r0c + rl]);
    #pragma unroll
    for (int tt = 0; tt < 8; tt++) {
        const int tgl = t0 + tl + tt;
        if (tgl < TLEN) {
            const float2 lo = unpk(accL[tt]);
            const float2 hi = unpk(accH[tt]);
            float4 outv = make_float4(lo.x + bv.x, lo.y + bv.y, hi.x + bv.z, hi.y + bv.w);
            *reinterpret_cast<float4*>(&g_gi[(b * TLEN + tgl) * NR + r0c + rl]) = outv;
        }
    }
}

// ============================================================================
// Kernel 3: AUGRU scan.  Whh^T in shared (192KB).  One block = 16 batches.
// Warp tile: 8 batches x 64 r (12 warps = 2 bb-groups x 6 r-groups).
// Lane owns an r-PAIR (f32x2) x 8 batches: weight fetch is a distinct-per-lane
// LDS.64 (256B/warp = 2 crossbar cyc, no dedup assumption).  x loads uniform.
// ============================================================================
#define REC_SMEM ((HD * NR + NB * SHP + NB * SG2P + NB) * 4 + NB * 4)

__global__ void __launch_bounds__(384, 1) rec_kernel(
    const float* __restrict__ Whh, const float* __restrict__ bhh,
    const int* __restrict__ klen, float* __restrict__ out)
{
    extern __shared__ float sm[];
    float* sWt  = sm;                       // [128][384]  Whh^T (k-major rows)
    float* sh   = sm + HD * NR;             // [16][SHP]   hidden state
    float* sg2  = sh + NB * SHP;            // [16][SG2P]  Whh.h + bhh
    float* satt = sg2 + NB * SG2P;          // [16]
    int*   slen = (int*)(satt + NB);        // [16]
    __shared__ int smax;

    const int tid = threadIdx.x;
    const int b0  = blockIdx.x * NB;

    for (int idx = tid; idx < NR * HD; idx += 384) {
        const int r = idx >> 7, j = idx & 127;
        sWt[j * NR + r] = Whh[idx];
    }
    if (tid < NB) slen[tid] = klen[b0 + tid];
    for (int i = tid; i < NB * SHP; i += 384) sh[i] = 0.0f;
    __syncthreads();
    if (tid == 0) {
        int m = 0;
        #pragma unroll
        for (int b = 0; b < NB; b++) m = max(m, slen[b]);
        smax = m;
    }
    __syncthreads();
    const int tmax = smax;

    // warp = (bg 0..1) * 6 + (rg 0..5); lane -> r-pair within rg's 64 rows
    const int lane = tid & 31, warp = tid >> 5;
    const int bg = warp / 6;                 // 0..1 -> batches bg*8..bg*8+7
    const int rg = warp - bg * 6;            // 0..5 -> rows rg*64..rg*64+63
    const int rl = rg * 64 + (lane >> 1) * 4 + (lane & 1) * 2;  // even, r-pair base
    const int bbase = bg * 8;
    const unsigned long long myb =
        *reinterpret_cast<const unsigned long long*>(&bhh[rl]);

    for (int t = 0; t < tmax; t++) {
        // ---- prefetch gi (bih folded in) and att for this step ----
        float pr[6], pz[6], pn[6];
        #pragma unroll
        for (int k = 0; k < 6; k++) {
            const int i = tid + k * 384;
            if (i < NB * HD) {
                const int bb = i >> 7, j = i & 127;
                const float* g = &g_gi[((b0 + bb) * TLEN + t) * NR + j];
                pr[k] = g[0];
                pz[k] = g[HD];
                pn[k] = g[2 * HD];
            }
        }
        if (tid < NB) satt[tid] = g_att[(b0 + tid) * TLEN + t];

        // ---- hidden GEMM: sg2 = h @ Whh^T + bhh ----
        unsigned long long acc[8];
        #pragma unroll
        for (int i = 0; i < 8; i++) acc[i] = myb;

        #pragma unroll 4
        for (int jc = 0; jc < HD / 4; jc++) {
            float4 x[8];
            #pragma unroll
            for (int i = 0; i < 8; i++)
                x[i] = *reinterpret_cast<const float4*>(&sh[(bbase + i) * SHP + jc * 4]);
            #pragma unroll
            for (int jj = 0; jj < 4; jj++) {
                const unsigned long long w =
                    *reinterpret_cast<const unsigned long long*>(
                        &sWt[(jc * 4 + jj) * NR + rl]);
                #pragma unroll
                for (int i = 0; i < 8; i++) {
                    const float xv = (jj == 0) ? x[i].x : (jj == 1) ? x[i].y
                                   : (jj == 2) ? x[i].z : x[i].w;
                    acc[i] = ffma2(w, dup2(xv), acc[i]);
                }
            }
        }
        #pragma unroll
        for (int i = 0; i < 8; i++)
            *reinterpret_cast<unsigned long long*>(&sg2[(bbase + i) * SG2P + rl]) = acc[i];
        __syncthreads();

        // ---- gated update (freeze past sequence end) ----
        #pragma unroll
        for (int k = 0; k < 6; k++) {
            const int i = tid + k * 384;
            if (i < NB * HD) {
                const int bb = i >> 7, j = i & 127;
                if (t < slen[bb]) {
                    const float g2r = sg2[bb * SG2P + j];
                    const float g2z = sg2[bb * SG2P + HD + j];
                    const float g2n = sg2[bb * SG2P + 2 * HD + j];
                    const float rr = sigm_t(pr[k] + g2r);
                    const float zz = sigm_t(pz[k] + g2z) * satt[bb];
                    const float nn = tanh_fast(pn[k] + rr * g2n);
                    sh[bb * SHP + j] = (1.0f - zz) * sh[bb * SHP + j] + zz * nn;
                }
            }
        }
        __syncthreads();
    }

    for (int i = tid; i < NB * HD; i += 384) {
        const int bb = i >> 7, j = i & 127;
        out[(b0 + bb) * HD + j] = (slen[bb] > 0) ? sh[bb * SHP + j] : 0.0f;
    }
}

// ============================================================================
extern "C" void kernel_launch(void* const* d_in, const int* in_sizes, int n_in,
                              void* d_out, int out_size)
{
    const float* query = (const float*)d_in[0];
    const float* keys  = (const float*)d_in[1];
    const float* W0    = (const float*)d_in[2];
    const float* b0    = (const float*)d_in[3];
    const float* W1    = (const float*)d_in[4];
    const float* b1    = (const float*)d_in[5];
    const float* Wd    = (const float*)d_in[6];
    const float* bd    = (const float*)d_in[7];
    const float* Wih   = (const float*)d_in[8];
    const float* Whh   = (const float*)d_in[9];
    const float* bih   = (const float*)d_in[10];
    const float* bhh   = (const float*)d_in[11];
    const int*   klen  = (const int*)d_in[12];
    float* out = (float*)d_out;

    cudaFuncSetAttribute(gi_kernel,  cudaFuncAttributeMaxDynamicSharedMemorySize, GI_SMEM);
    cudaFuncSetAttribute(rec_kernel, cudaFuncAttributeMaxDynamicSharedMemorySize, REC_SMEM);

    qpart_kernel<<<BATCH / NB, 256>>>(query, W0, b0);
    attn_kernel<<<BATCH, 256>>>(query, keys, W0, W1, b1, Wd, bd, klen);
    gi_kernel<<<dim3(4, 3, BATCH), 256, GI_SMEM>>>(keys, Wih, bih, klen);
    rec_kernel<<<RBLK, 384, REC_SMEM>>>(Whh, bhh, klen, out);
}

// round 6
// speedup vs baseline: 3.7330x; 1.3922x over previous
#include <cuda_runtime.h>
#include <cuda_bf16.h>
#include <cstdint>

#define BATCH 2048
#define TLEN  200
#define HD    128
#define NA0   64
#define NA1   16
#define TT    8
#define NB    16
#define RBLK  (BATCH / NB)   // 128 scan blocks
#define NR    384            // 3*HD gate rows
#define SG2P  386            // sg2 pitch (floats), even
#define APITCH 136           // bf16 A pitch: 272B rows -> conflict-free ldmatrix

// ---------------- device scratch (no allocs allowed) ----------------
__device__ float g_att[BATCH * TLEN];            // 1.6 MB attention scores
__device__ float g_qp [BATCH * NA0];             // 0.5 MB qpart
__device__ float g_gi [BATCH * TLEN * NR];       // 629 MB  gi = keys@Wih^T + bih

// ---------------- packed f32x2 helpers ----------------
__device__ __forceinline__ unsigned long long ffma2(unsigned long long a,
                                                    unsigned long long b,
                                                    unsigned long long c) {
    unsigned long long d;
    asm("fma.rn.f32x2 %0, %1, %2, %3;" : "=l"(d) : "l"(a), "l"(b), "l"(c));
    return d;
}
__device__ __forceinline__ unsigned long long dup2(float x) {
    unsigned long long d;
    asm("mov.b64 %0, {%1, %1};" : "=l"(d) : "f"(x));
    return d;
}
__device__ __forceinline__ float2 unpk(unsigned long long v) {
    float2 f;
    asm("mov.b64 {%0, %1}, %2;" : "=f"(f.x), "=f"(f.y) : "l"(v));
    return f;
}
__device__ __forceinline__ float sigm(float x) {
    return __fdividef(1.0f, 1.0f + __expf(-x));
}
__device__ __forceinline__ float tanh_fast(float x) {
    float y;
    asm("tanh.approx.f32 %0, %1;" : "=f"(y) : "f"(x));
    return y;
}
__device__ __forceinline__ float sigm_t(float x) {
    return fmaf(0.5f, tanh_fast(0.5f * x), 0.5f);
}
__device__ __forceinline__ uint32_t pkbf(float lo, float hi) {
    __nv_bfloat16 a = __float2bfloat16(lo), b = __float2bfloat16(hi);
    uint16_t ua = *reinterpret_cast<uint16_t*>(&a);
    uint16_t ub = *reinterpret_cast<uint16_t*>(&b);
    return (uint32_t)ua | ((uint32_t)ub << 16);
}
// m16n8k16 bf16 MMA, f32 accumulate
__device__ __forceinline__ void mma16816(float& c0, float& c1, float& c2, float& c3,
                                         uint32_t a0, uint32_t a1, uint32_t a2, uint32_t a3,
                                         uint32_t b0, uint32_t b1) {
    asm volatile(
        "mma.sync.aligned.m16n8k16.row.col.f32.bf16.bf16.f32 "
        "{%0,%1,%2,%3}, {%4,%5,%6,%7}, {%8,%9}, {%0,%1,%2,%3};"
        : "+f"(c0), "+f"(c1), "+f"(c2), "+f"(c3)
        : "r"(a0), "r"(a1), "r"(a2), "r"(a3), "r"(b0), "r"(b1));
}
__device__ __forceinline__ void ldmx4(uint32_t& r0, uint32_t& r1, uint32_t& r2, uint32_t& r3,
                                      uint32_t addr) {
    asm volatile("ldmatrix.sync.aligned.m8n8.x4.shared.b16 {%0,%1,%2,%3}, [%4];"
                 : "=r"(r0), "=r"(r1), "=r"(r2), "=r"(r3) : "r"(addr));
}

// ============================================================================
// Kernel 0: qpart[b][o] = b0[o] + sum_j (W0a[o,j]+W0c[o,j]) * q[b][j]
// ============================================================================
__global__ void __launch_bounds__(256) qpart_kernel(
    const float* __restrict__ query, const float* __restrict__ W0,
    const float* __restrict__ b0)
{
    __shared__ float sWeff[NA0 * 132];
    __shared__ float sqq[NB * HD];

    const int tid = threadIdx.x;
    const int b0i = blockIdx.x * NB;

    for (int idx = tid; idx < NA0 * HD; idx += 256) {
        const int o = idx >> 7, j = idx & 127;
        sWeff[o * 132 + j] = W0[o * (4 * HD) + j] + W0[o * (4 * HD) + 2 * HD + j];
    }
    for (int idx = tid; idx < NB * HD; idx += 256)
        sqq[idx] = query[b0i * HD + idx];
    __syncthreads();

    const int o  = tid & 63;
    const int bg = tid >> 6;
    unsigned long long acc[4];
    #pragma unroll
    for (int i = 0; i < 4; i++) acc[i] = 0ull;

    #pragma unroll 4
    for (int jc = 0; jc < HD / 4; jc++) {
        const ulonglong2 w = *reinterpret_cast<const ulonglong2*>(&sWeff[o * 132 + jc * 4]);
        #pragma unroll
        for (int i = 0; i < 4; i++) {
            const ulonglong2 x =
                *reinterpret_cast<const ulonglong2*>(&sqq[(bg * 4 + i) * HD + jc * 4]);
            acc[i] = ffma2(w.x, x.x, acc[i]);
            acc[i] = ffma2(w.y, x.y, acc[i]);
        }
    }
    const float bo = b0[o];
    #pragma unroll
    for (int i = 0; i < 4; i++) {
        const float2 p = unpk(acc[i]);
        g_qp[(b0i + bg * 4 + i) * NA0 + o] = p.x + p.y + bo;
    }
}

// ============================================================================
// Kernel 1: DIN attention MLP (one block per batch).
// ============================================================================
__global__ void __launch_bounds__(256) attn_kernel(
    const float* __restrict__ query, const float* __restrict__ keys,
    const float* __restrict__ W0,
    const float* __restrict__ W1, const float* __restrict__ b1,
    const float* __restrict__ Wd, const float* __restrict__ bd,
    const int* __restrict__ klen)
{
    __shared__ float sq[HD];
    __shared__ float sWk[NA0 * 132];
    __shared__ float sqp[NA0];
    __shared__ float skey[TT * 132];
    __shared__ float sa0[TT * 68];
    __shared__ float sa1[TT * NA1];
    __shared__ float sW1[NA1 * NA0];
    __shared__ float sWd[NA1];
    __shared__ float sb1[NA1];

    const int b    = blockIdx.x;
    const int tid  = threadIdx.x;
    const int lenb = klen[b];

    if (tid < HD) sq[tid] = query[b * HD + tid];
    if (tid < NA1) { sWd[tid] = Wd[tid]; sb1[tid] = b1[tid]; }
    if (tid < NA0) sqp[tid] = g_qp[b * NA0 + tid];
    for (int i = tid; i < NA1 * NA0; i += 256) sW1[i] = W1[i];
    __syncthreads();

    for (int idx = tid; idx < NA0 * HD; idx += 256) {
        const int o = idx >> 7, j = idx & 127;
        const float* w = W0 + o * (4 * HD);
        sWk[o * 132 + j] = w[HD + j] - w[2 * HD + j] + w[3 * HD + j] * sq[j];
    }
    __syncthreads();

    const int warp = tid >> 5, lane = tid & 31;

    for (int t0 = 0; t0 < TLEN; t0 += TT) {
        if (t0 >= lenb) {
            if (tid < TT) g_att[b * TLEN + t0 + tid] = 0.0f;
            continue;
        }
        for (int idx = tid; idx < TT * HD; idx += 256) {
            const int tt = idx >> 7, j = idx & 127;
            skey[tt * 132 + j] = keys[(b * TLEN + t0 + tt) * HD + j];
        }
        __syncthreads();

        {
            unsigned long long acc0a = 0ull, acc0b = 0ull, acc1a = 0ull, acc1b = 0ull;
            const ulonglong2* kp  = reinterpret_cast<const ulonglong2*>(&skey[warp * 132]);
            const ulonglong2* w0p = reinterpret_cast<const ulonglong2*>(&sWk[lane * 132]);
            const ulonglong2* w1p = reinterpret_cast<const ulonglong2*>(&sWk[(lane + 32) * 132]);
            #pragma unroll 8
            for (int jc = 0; jc < HD / 4; jc++) {
                ulonglong2 x  = kp[jc];
                ulonglong2 wa = w0p[jc];
                ulonglong2 wb = w1p[jc];
                acc0a = ffma2(wa.x, x.x, acc0a);
                acc0b = ffma2(wa.y, x.y, acc0b);
                acc1a = ffma2(wb.x, x.x, acc1a);
                acc1b = ffma2(wb.y, x.y, acc1b);
            }
            float2 p = unpk(acc0a), q2 = unpk(acc0b);
            const float s0 = p.x + p.y + q2.x + q2.y + sqp[lane];
            p = unpk(acc1a); q2 = unpk(acc1b);
            const float s1 = p.x + p.y + q2.x + q2.y + sqp[lane + 32];
            sa0[warp * 68 + lane]      = sigm(s0);
            sa0[warp * 68 + lane + 32] = sigm(s1);
        }
        __syncthreads();

        if (tid < TT * NA1) {
            const int tt = tid >> 4, p = tid & 15;
            float s = sb1[p];
            #pragma unroll 8
            for (int o = 0; o < NA0; o++) s += sW1[p * NA0 + o] * sa0[tt * 68 + o];
            sa1[tt * NA1 + p] = sigm(s);
        }
        __syncthreads();

        if (tid < TT) {
            float s = bd[0];
            #pragma unroll
            for (int p = 0; p < NA1; p++) s += sWd[p] * sa1[tid * NA1 + p];
            g_att[b * TLEN + t0 + tid] = (t0 + tid < lenb) ? s : 0.0f;
        }
        __syncthreads();
    }
}

// ============================================================================
// Kernel 2: gi GEMM.  g_gi[b][t][r] = keys[b][t][:] . Wih[r][:] + bih[r]
// ============================================================================
#define GI_SMEM ((64 * 132 + 128 * 132) * 4)

__global__ void __launch_bounds__(256) gi_kernel(
    const float* __restrict__ keys, const float* __restrict__ Wih,
    const float* __restrict__ bih, const int* __restrict__ klen)
{
    extern __shared__ float gsm[];
    float* sA  = gsm;               // [64][132]  keys tile (t-major)
    float* sBt = gsm + 64 * 132;    // [128][132] Wih^T tile (j-major)

    const int b   = blockIdx.z;
    const int t0  = blockIdx.x * 64;
    const int r0c = blockIdx.y * 128;
    const int lenb = klen[b];
    if (t0 >= lenb) return;

    const int tid = threadIdx.x;

    for (int idx = tid; idx < 64 * HD; idx += 256) {
        const int tt = idx >> 7, j = idx & 127;
        const int tg = t0 + tt;
        sA[tt * 132 + j] = (tg < TLEN) ? keys[(b * TLEN + tg) * HD + j] : 0.0f;
    }
    for (int idx = tid; idx < 128 * HD; idx += 256) {
        const int rr = idx >> 7, j = idx & 127;
        sBt[j * 132 + rr] = Wih[(r0c + rr) * HD + j];
    }
    __syncthreads();

    const int rq = tid & 31;
    const int tg = tid >> 5;
    const int rl = rq * 4;
    const int tl = tg * 8;

    if (t0 + tl >= lenb) return;

    unsigned long long accL[8], accH[8];
    #pragma unroll
    for (int i = 0; i < 8; i++) { accL[i] = 0ull; accH[i] = 0ull; }

    #pragma unroll 2
    for (int jc = 0; jc < HD / 4; jc++) {
        float4 a[8];
        #pragma unroll
        for (int tt = 0; tt < 8; tt++)
            a[tt] = *reinterpret_cast<const float4*>(&sA[(tl + tt) * 132 + jc * 4]);
        #pragma unroll
        for (int jj = 0; jj < 4; jj++) {
            const ulonglong2 w =
                *reinterpret_cast<const ulonglong2*>(&sBt[(jc * 4 + jj) * 132 + rl]);
            #pragma unroll
            for (int tt = 0; tt < 8; tt++) {
                const float av = (jj == 0) ? a[tt].x : (jj == 1) ? a[tt].y
                               : (jj == 2) ? a[tt].z : a[tt].w;
                const unsigned long long d = dup2(av);
                accL[tt] = ffma2(w.x, d, accL[tt]);
                accH[tt] = ffma2(w.y, d, accH[tt]);
            }
        }
    }

    const float4 bv = *reinterpret_cast<const float4*>(&bih[r0c + rl]);
    #pragma unroll
    for (int tt = 0; tt < 8; tt++) {
        const int tgl = t0 + tl + tt;
        if (tgl < TLEN) {
            const float2 lo = unpk(accL[tt]);
            const float2 hi = unpk(accH[tt]);
            float4 outv = make_float4(lo.x + bv.x, lo.y + bv.y, hi.x + bv.z, hi.y + bv.w);
            *reinterpret_cast<float4*>(&g_gi[(b * TLEN + tgl) * NR + r0c + rl]) = outv;
        }
    }
}

// ============================================================================
// Kernel 3: AUGRU scan via tensor cores (mma.sync m16n8k16 bf16, 3-term split).
// 128 blocks x 512 threads (16 warps).  Block = 16 batches (M=16).
// Warp w owns n-slice [w*24, w*24+24) = 3 n-tiles of 8.
// B (Whh) hi/lo pre-converted into per-(warp,kc,nt,lane) fragment order in smem.
// A (=h) hi/lo bf16 arrays, pitch 136 -> conflict-free ldmatrix.x4.
// h master copy in f32 registers of the update threads (4 elems each).
// ============================================================================
#define NWARP 16
#define NTW   3                    // n-tiles per warp
#define NFRAG (NWARP * 8 * NTW)    // 384 fragments total
// smem offsets (bytes)
#define OFF_BHI  0
#define OFF_BLO  (NFRAG * 32 * 8)                     // 98304
#define OFF_AHI  (OFF_BLO + NFRAG * 32 * 8)           // 196608
#define OFF_ALO  (OFF_AHI + NB * APITCH * 2)          // 200960
#define OFF_SG2  (OFF_ALO + NB * APITCH * 2)          // 205312
#define OFF_ATT  (OFF_SG2 + NB * SG2P * 4)            // 230016
#define OFF_LEN  (OFF_ATT + NB * 4)                   // 230080
#define REC_SMEM (OFF_LEN + NB * 4)                   // 230144

__global__ void __launch_bounds__(512, 1) rec_kernel(
    const float* __restrict__ Whh, const float* __restrict__ bhh,
    const int* __restrict__ klen, float* __restrict__ out)
{
    extern __shared__ char smc[];
    uint2* sBhi = reinterpret_cast<uint2*>(smc + OFF_BHI);
    uint2* sBlo = reinterpret_cast<uint2*>(smc + OFF_BLO);
    __nv_bfloat16* sAhi = reinterpret_cast<__nv_bfloat16*>(smc + OFF_AHI);
    __nv_bfloat16* sAlo = reinterpret_cast<__nv_bfloat16*>(smc + OFF_ALO);
    float* sg2  = reinterpret_cast<float*>(smc + OFF_SG2);
    float* satt = reinterpret_cast<float*>(smc + OFF_ATT);
    int*   slen = reinterpret_cast<int*>(smc + OFF_LEN);
    __shared__ int smax;

    const int tid  = threadIdx.x;
    const int lane = tid & 31, warp = tid >> 5;
    const int gid  = lane >> 2, tig = lane & 3;
    const int b0   = blockIdx.x * NB;

    // ---- build B fragments (hi/lo) once ----
    #pragma unroll
    for (int kc = 0; kc < 8; kc++) {
        #pragma unroll
        for (int nt = 0; nt < NTW; nt++) {
            const int n = warp * 24 + nt * 8 + gid;
            const float* wr = Whh + n * HD + kc * 16;
            const float w0 = wr[2 * tig],     w1 = wr[2 * tig + 1];
            const float w2 = wr[2 * tig + 8], w3 = wr[2 * tig + 9];
            const __nv_bfloat16 h0 = __float2bfloat16(w0), h1 = __float2bfloat16(w1);
            const __nv_bfloat16 h2 = __float2bfloat16(w2), h3 = __float2bfloat16(w3);
            const int idx = ((warp * 8 + kc) * NTW + nt) * 32 + lane;
            sBhi[idx] = make_uint2(pkbf(w0, w1), pkbf(w2, w3));   // hi parts
            sBlo[idx] = make_uint2(
                pkbf(w0 - __bfloat162float(h0), w1 - __bfloat162float(h1)),
                pkbf(w2 - __bfloat162float(h2), w3 - __bfloat162float(h3)));
        }
    }
    // zero A arrays
    for (int i = tid; i < NB * APITCH; i += 512) {
        sAhi[i] = __float2bfloat16(0.0f);
        sAlo[i] = __float2bfloat16(0.0f);
    }
    if (tid < NB) slen[tid] = klen[b0 + tid];
    __syncthreads();
    if (tid == 0) {
        int m = 0;
        #pragma unroll
        for (int b = 0; b < NB; b++) m = max(m, slen[b]);
        smax = m;
    }
    __syncthreads();
    const int tmax = smax;

    // ldmatrix per-lane base addresses (tile m = lane>>3, row r = lane&7)
    const int lm_m = lane >> 3, lm_r = lane & 7;
    const int lm_row = ((lm_m & 1) ? 8 : 0) + lm_r;
    const int lm_col = (lm_m >> 1) * 8;
    const uint32_t aoff = (uint32_t)((lm_row * APITCH + lm_col) * 2);
    const uint32_t ahi_base = (uint32_t)__cvta_generic_to_shared(sAhi) + aoff;
    const uint32_t alo_base = (uint32_t)__cvta_generic_to_shared(sAlo) + aoff;

    // bias per n-tile columns
    float cb0[NTW], cb1[NTW];
    #pragma unroll
    for (int nt = 0; nt < NTW; nt++) {
        cb0[nt] = bhh[warp * 24 + nt * 8 + 2 * tig];
        cb1[nt] = bhh[warp * 24 + nt * 8 + 2 * tig + 1];
    }

    float hreg[4] = {0.0f, 0.0f, 0.0f, 0.0f};

    for (int t = 0; t < tmax; t++) {
        // ---- prefetch gi and att ----
        float pr[4], pz[4], pn[4];
        #pragma unroll
        for (int k = 0; k < 4; k++) {
            const int i = tid + k * 512;
            const int bb = i >> 7, j = i & 127;
            const float* g = &g_gi[((b0 + bb) * TLEN + t) * NR + j];
            pr[k] = g[0];
            pz[k] = g[HD];
            pn[k] = g[2 * HD];
        }
        if (tid < NB) satt[tid] = g_att[(b0 + tid) * TLEN + t];

        // ---- tensor GEMM: sg2 = h @ Whh^T + bhh (3-term bf16 split) ----
        float c[NTW][4];
        #pragma unroll
        for (int nt = 0; nt < NTW; nt++) {
            c[nt][0] = cb0[nt]; c[nt][1] = cb1[nt];
            c[nt][2] = cb0[nt]; c[nt][3] = cb1[nt];
        }
        #pragma unroll
        for (int kc = 0; kc < 8; kc++) {
            uint32_t ah0, ah1, ah2, ah3, al0, al1, al2, al3;
            ldmx4(ah0, ah1, ah2, ah3, ahi_base + kc * 32);
            ldmx4(al0, al1, al2, al3, alo_base + kc * 32);
            #pragma unroll
            for (int nt = 0; nt < NTW; nt++) {
                const int idx = ((warp * 8 + kc) * NTW + nt) * 32 + lane;
                const uint2 bh = sBhi[idx];
                const uint2 bl = sBlo[idx];
                mma16816(c[nt][0], c[nt][1], c[nt][2], c[nt][3],
                         ah0, ah1, ah2, ah3, bh.x, bh.y);
                mma16816(c[nt][0], c[nt][1], c[nt][2], c[nt][3],
                         al0, al1, al2, al3, bh.x, bh.y);
                mma16816(c[nt][0], c[nt][1], c[nt][2], c[nt][3],
                         ah0, ah1, ah2, ah3, bl.x, bl.y);
            }
        }
        #pragma unroll
        for (int nt = 0; nt < NTW; nt++) {
            const int colb = warp * 24 + nt * 8 + 2 * tig;
            *reinterpret_cast<float2*>(&sg2[gid * SG2P + colb]) =
                make_float2(c[nt][0], c[nt][1]);
            *reinterpret_cast<float2*>(&sg2[(gid + 8) * SG2P + colb]) =
                make_float2(c[nt][2], c[nt][3]);
        }
        __syncthreads();

        // ---- gated update (freeze past sequence end) ----
        #pragma unroll
        for (int k = 0; k < 4; k++) {
            const int i = tid + k * 512;
            const int bb = i >> 7, j = i & 127;
            if (t < slen[bb]) {
                const float g2r = sg2[bb * SG2P + j];
                const float g2z = sg2[bb * SG2P + HD + j];
                const float g2n = sg2[bb * SG2P + 2 * HD + j];
                const float rr = sigm_t(pr[k] + g2r);
                const float zz = sigm_t(pz[k] + g2z) * satt[bb];
                const float nn = tanh_fast(pn[k] + rr * g2n);
                const float hn = (1.0f - zz) * hreg[k] + zz * nn;
                hreg[k] = hn;
                const __nv_bfloat16 hb = __float2bfloat16(hn);
                sAhi[bb * APITCH + j] = hb;
                sAlo[bb * APITCH + j] = __float2bfloat16(hn - __bfloat162float(hb));
            }
        }
        __syncthreads();
    }

    #pragma unroll
    for (int k = 0; k < 4; k++) {
        const int i = tid + k * 512;
        const int bb = i >> 7, j = i & 127;
        out[(b0 + bb) * HD + j] = (slen[bb] > 0) ? hreg[k] : 0.0f;
    }
}

// ============================================================================
extern "C" void kernel_launch(void* const* d_in, const int* in_sizes, int n_in,
                              void* d_out, int out_size)
{
    const float* query = (const float*)d_in[0];
    const float* keys  = (const float*)d_in[1];
    const float* W0    = (const float*)d_in[2];
    const float* b0    = (const float*)d_in[3];
    const float* W1    = (const float*)d_in[4];
    const float* b1    = (const float*)d_in[5];
    const float* Wd    = (const float*)d_in[6];
    const float* bd    = (const float*)d_in[7];
    const float* Wih   = (const float*)d_in[8];
    const float* Whh   = (const float*)d_in[9];
    const float* bih   = (const float*)d_in[10];
    const float* bhh   = (const float*)d_in[11];
    const int*   klen  = (const int*)d_in[12];
    float* out = (float*)d_out;

    cudaFuncSetAttribute(gi_kernel,  cudaFuncAttributeMaxDynamicSharedMemorySize, GI_SMEM);
    cudaFuncSetAttribute(rec_kernel, cudaFuncAttributeMaxDynamicSharedMemorySize, REC_SMEM);

    qpart_kernel<<<BATCH / NB, 256>>>(query, W0, b0);
    attn_kernel<<<BATCH, 256>>>(query, keys, W0, W1, b1, Wd, bd, klen);
    gi_kernel<<<dim3(4, 3, BATCH), 256, GI_SMEM>>>(keys, Wih, bih, klen);
    rec_kernel<<<RBLK, 512, REC_SMEM>>>(Whh, bhh, klen, out);
}

// round 7
// speedup vs baseline: 4.4954x; 1.2042x over previous
#include <cuda_runtime.h>
#include <cuda_bf16.h>
#include <cstdint>

#define BATCH 2048
#define TLEN  200
#define HD    128
#define NA0   64
#define NA1   16
#define TT    8
#define NB    16
#define RBLK  (BATCH / NB)   // 128 scan blocks
#define NR    384            // 3*HD gate rows
#define SG2P  386            // sg2 pitch (floats), even
#define APITCH 136           // bf16 A pitch: 272B rows -> conflict-free ldmatrix

// ---------------- device scratch (no allocs allowed) ----------------
__device__ float g_att[BATCH * TLEN];            // 1.6 MB attention scores
__device__ float g_qp [BATCH * NA0];             // 0.5 MB qpart
__device__ float g_gi [BATCH * TLEN * NR];       // 629 MB  gi = keys@Wih^T + bih
__device__ uint2 g_wfhi[48 * 8 * 32];            // Wih hi fragments (98KB)
__device__ uint2 g_wflo[48 * 8 * 32];            // Wih lo fragments (98KB)

// ---------------- packed f32x2 helpers ----------------
__device__ __forceinline__ unsigned long long ffma2(unsigned long long a,
                                                    unsigned long long b,
                                                    unsigned long long c) {
    unsigned long long d;
    asm("fma.rn.f32x2 %0, %1, %2, %3;" : "=l"(d) : "l"(a), "l"(b), "l"(c));
    return d;
}
__device__ __forceinline__ float2 unpk(unsigned long long v) {
    float2 f;
    asm("mov.b64 {%0, %1}, %2;" : "=f"(f.x), "=f"(f.y) : "l"(v));
    return f;
}
__device__ __forceinline__ float sigm(float x) {
    return __fdividef(1.0f, 1.0f + __expf(-x));
}
__device__ __forceinline__ float tanh_fast(float x) {
    float y;
    asm("tanh.approx.f32 %0, %1;" : "=f"(y) : "f"(x));
    return y;
}
__device__ __forceinline__ float sigm_t(float x) {
    return fmaf(0.5f, tanh_fast(0.5f * x), 0.5f);
}
__device__ __forceinline__ uint32_t pkbf(float lo, float hi) {
    __nv_bfloat16 a = __float2bfloat16(lo), b = __float2bfloat16(hi);
    uint16_t ua = *reinterpret_cast<uint16_t*>(&a);
    uint16_t ub = *reinterpret_cast<uint16_t*>(&b);
    return (uint32_t)ua | ((uint32_t)ub << 16);
}
__device__ __forceinline__ void mma16816(float& c0, float& c1, float& c2, float& c3,
                                         uint32_t a0, uint32_t a1, uint32_t a2, uint32_t a3,
                                         uint32_t b0, uint32_t b1) {
    asm volatile(
        "mma.sync.aligned.m16n8k16.row.col.f32.bf16.bf16.f32 "
        "{%0,%1,%2,%3}, {%4,%5,%6,%7}, {%8,%9}, {%0,%1,%2,%3};"
        : "+f"(c0), "+f"(c1), "+f"(c2), "+f"(c3)
        : "r"(a0), "r"(a1), "r"(a2), "r"(a3), "r"(b0), "r"(b1));
}
__device__ __forceinline__ void ldmx4(uint32_t& r0, uint32_t& r1, uint32_t& r2, uint32_t& r3,
                                      uint32_t addr) {
    asm volatile("ldmatrix.sync.aligned.m8n8.x4.shared.b16 {%0,%1,%2,%3}, [%4];"
                 : "=r"(r0), "=r"(r1), "=r"(r2), "=r"(r3) : "r"(addr));
}

// ============================================================================
// Kernel W: build Wih bf16 hi/lo fragments in global (once, L2-resident after).
// grid=48 n-tiles, block=256 (8 warps = 8 kc).  Same frag layout as rec's B.
// ============================================================================
__global__ void __launch_bounds__(256) wfrag_kernel(const float* __restrict__ Wih)
{
    const int nt   = blockIdx.x;          // 0..47
    const int tid  = threadIdx.x;
    const int kc   = tid >> 5;            // 0..7
    const int lane = tid & 31;
    const int gid  = lane >> 2, tig = lane & 3;

    const int n = nt * 8 + gid;
    const float* wr = Wih + n * HD + kc * 16;
    const float w0 = wr[2 * tig],     w1 = wr[2 * tig + 1];
    const float w2 = wr[2 * tig + 8], w3 = wr[2 * tig + 9];
    const __nv_bfloat16 h0 = __float2bfloat16(w0), h1 = __float2bfloat16(w1);
    const __nv_bfloat16 h2 = __float2bfloat16(w2), h3 = __float2bfloat16(w3);
    const int idx = (nt * 8 + kc) * 32 + lane;
    g_wfhi[idx] = make_uint2(pkbf(w0, w1), pkbf(w2, w3));
    g_wflo[idx] = make_uint2(
        pkbf(w0 - __bfloat162float(h0), w1 - __bfloat162float(h1)),
        pkbf(w2 - __bfloat162float(h2), w3 - __bfloat162float(h3)));
}

// ============================================================================
// Kernel 0: qpart[b][o] = b0[o] + sum_j (W0a[o,j]+W0c[o,j]) * q[b][j]
// ============================================================================
__global__ void __launch_bounds__(256) qpart_kernel(
    const float* __restrict__ query, const float* __restrict__ W0,
    const float* __restrict__ b0)
{
    __shared__ float sWeff[NA0 * 132];
    __shared__ float sqq[NB * HD];

    const int tid = threadIdx.x;
    const int b0i = blockIdx.x * NB;

    for (int idx = tid; idx < NA0 * HD; idx += 256) {
        const int o = idx >> 7, j = idx & 127;
        sWeff[o * 132 + j] = W0[o * (4 * HD) + j] + W0[o * (4 * HD) + 2 * HD + j];
    }
    for (int idx = tid; idx < NB * HD; idx += 256)
        sqq[idx] = query[b0i * HD + idx];
    __syncthreads();

    const int o  = tid & 63;
    const int bg = tid >> 6;
    unsigned long long acc[4];
    #pragma unroll
    for (int i = 0; i < 4; i++) acc[i] = 0ull;

    #pragma unroll 4
    for (int jc = 0; jc < HD / 4; jc++) {
        const ulonglong2 w = *reinterpret_cast<const ulonglong2*>(&sWeff[o * 132 + jc * 4]);
        #pragma unroll
        for (int i = 0; i < 4; i++) {
            const ulonglong2 x =
                *reinterpret_cast<const ulonglong2*>(&sqq[(bg * 4 + i) * HD + jc * 4]);
            acc[i] = ffma2(w.x, x.x, acc[i]);
            acc[i] = ffma2(w.y, x.y, acc[i]);
        }
    }
    const float bo = b0[o];
    #pragma unroll
    for (int i = 0; i < 4; i++) {
        const float2 p = unpk(acc[i]);
        g_qp[(b0i + bg * 4 + i) * NA0 + o] = p.x + p.y + bo;
    }
}

// ============================================================================
// Kernel 1: DIN attention MLP (one block per batch).
// ============================================================================
__global__ void __launch_bounds__(256) attn_kernel(
    const float* __restrict__ query, const float* __restrict__ keys,
    const float* __restrict__ W0,
    const float* __restrict__ W1, const float* __restrict__ b1,
    const float* __restrict__ Wd, const float* __restrict__ bd,
    const int* __restrict__ klen)
{
    __shared__ float sq[HD];
    __shared__ float sWk[NA0 * 132];
    __shared__ float sqp[NA0];
    __shared__ float skey[TT * 132];
    __shared__ float sa0[TT * 68];
    __shared__ float sa1[TT * NA1];
    __shared__ float sW1[NA1 * NA0];
    __shared__ float sWd[NA1];
    __shared__ float sb1[NA1];

    const int b    = blockIdx.x;
    const int tid  = threadIdx.x;
    const int lenb = klen[b];

    if (tid < HD) sq[tid] = query[b * HD + tid];
    if (tid < NA1) { sWd[tid] = Wd[tid]; sb1[tid] = b1[tid]; }
    if (tid < NA0) sqp[tid] = g_qp[b * NA0 + tid];
    for (int i = tid; i < NA1 * NA0; i += 256) sW1[i] = W1[i];
    __syncthreads();

    for (int idx = tid; idx < NA0 * HD; idx += 256) {
        const int o = idx >> 7, j = idx & 127;
        const float* w = W0 + o * (4 * HD);
        sWk[o * 132 + j] = w[HD + j] - w[2 * HD + j] + w[3 * HD + j] * sq[j];
    }
    __syncthreads();

    const int warp = tid >> 5, lane = tid & 31;

    for (int t0 = 0; t0 < TLEN; t0 += TT) {
        if (t0 >= lenb) {
            if (tid < TT) g_att[b * TLEN + t0 + tid] = 0.0f;
            continue;
        }
        for (int idx = tid; idx < TT * HD; idx += 256) {
            const int tt = idx >> 7, j = idx & 127;
            skey[tt * 132 + j] = keys[(b * TLEN + t0 + tt) * HD + j];
        }
        __syncthreads();

        {
            unsigned long long acc0a = 0ull, acc0b = 0ull, acc1a = 0ull, acc1b = 0ull;
            const ulonglong2* kp  = reinterpret_cast<const ulonglong2*>(&skey[warp * 132]);
            const ulonglong2* w0p = reinterpret_cast<const ulonglong2*>(&sWk[lane * 132]);
            const ulonglong2* w1p = reinterpret_cast<const ulonglong2*>(&sWk[(lane + 32) * 132]);
            #pragma unroll 8
            for (int jc = 0; jc < HD / 4; jc++) {
                ulonglong2 x  = kp[jc];
                ulonglong2 wa = w0p[jc];
                ulonglong2 wb = w1p[jc];
                acc0a = ffma2(wa.x, x.x, acc0a);
                acc0b = ffma2(wa.y, x.y, acc0b);
                acc1a = ffma2(wb.x, x.x, acc1a);
                acc1b = ffma2(wb.y, x.y, acc1b);
            }
            float2 p = unpk(acc0a), q2 = unpk(acc0b);
            const float s0 = p.x + p.y + q2.x + q2.y + sqp[lane];
            p = unpk(acc1a); q2 = unpk(acc1b);
            const float s1 = p.x + p.y + q2.x + q2.y + sqp[lane + 32];
            sa0[warp * 68 + lane]      = sigm(s0);
            sa0[warp * 68 + lane + 32] = sigm(s1);
        }
        __syncthreads();

        if (tid < TT * NA1) {
            const int tt = tid >> 4, p = tid & 15;
            float s = sb1[p];
            #pragma unroll 8
            for (int o = 0; o < NA0; o++) s += sW1[p * NA0 + o] * sa0[tt * 68 + o];
            sa1[tt * NA1 + p] = sigm(s);
        }
        __syncthreads();

        if (tid < TT) {
            float s = bd[0];
            #pragma unroll
            for (int p = 0; p < NA1; p++) s += sWd[p] * sa1[tid * NA1 + p];
            g_att[b * TLEN + t0 + tid] = (t0 + tid < lenb) ? s : 0.0f;
        }
        __syncthreads();
    }
}

// ============================================================================
// Kernel 2: gi GEMM via tensor cores (3-term bf16 split).
// grid (4 t-tiles of 64, 3 r-tiles of 128, 2048 b), 256 threads (8 warps).
// Warp = (m-tile warp&3) x (n-half warp>>2, 8 n-tiles each).
// A = keys tile bf16 hi/lo in smem (ldmatrix.x4); B = prebuilt Wih fragments
// from global (coalesced LDG.64, L2-resident, reused across 4 m-tiles).
// ============================================================================
__global__ void __launch_bounds__(256) gi_kernel(
    const float* __restrict__ keys, const float* __restrict__ bih,
    const int* __restrict__ klen)
{
    __shared__ __nv_bfloat16 sAhi[64 * APITCH];
    __shared__ __nv_bfloat16 sAlo[64 * APITCH];

    const int b    = blockIdx.z;
    const int t0   = blockIdx.x * 64;
    const int r0   = blockIdx.y * 128;
    const int lenb = klen[b];
    if (t0 >= lenb) return;

    const int tid = threadIdx.x;

    // stage keys tile -> bf16 hi/lo
    for (int idx = tid; idx < 64 * HD; idx += 256) {
        const int tt = idx >> 7, j = idx & 127;
        const int tg = t0 + tt;
        const float v = (tg < TLEN) ? keys[(b * TLEN + tg) * HD + j] : 0.0f;
        const __nv_bfloat16 h = __float2bfloat16(v);
        sAhi[tt * APITCH + j] = h;
        sAlo[tt * APITCH + j] = __float2bfloat16(v - __bfloat162float(h));
    }
    __syncthreads();

    const int lane = tid & 31, warp = tid >> 5;
    const int gid  = lane >> 2, tig = lane & 3;
    const int mt   = warp & 3;            // m-tile (16 t-rows)
    const int nh   = warp >> 2;           // n-half (8 n-tiles of 8)

    const int lm_m = lane >> 3, lm_r = lane & 7;
    const int lm_row = mt * 16 + ((lm_m & 1) ? 8 : 0) + lm_r;
    const int lm_col = (lm_m >> 1) * 8;
    const uint32_t aoff = (uint32_t)((lm_row * APITCH + lm_col) * 2);
    const uint32_t ahi_base = (uint32_t)__cvta_generic_to_shared(sAhi) + aoff;
    const uint32_t alo_base = (uint32_t)__cvta_generic_to_shared(sAlo) + aoff;

    float c[8][4];
    #pragma unroll
    for (int nt = 0; nt < 8; nt++) {
        const int col = r0 + (nh * 8 + nt) * 8 + 2 * tig;
        const float bv0 = bih[col], bv1 = bih[col + 1];
        c[nt][0] = bv0; c[nt][1] = bv1; c[nt][2] = bv0; c[nt][3] = bv1;
    }

    const int ntg0 = (r0 >> 3) + nh * 8;   // global n-tile base for this warp

    #pragma unroll
    for (int kc = 0; kc < 8; kc++) {
        uint32_t ah0, ah1, ah2, ah3, al0, al1, al2, al3;
        ldmx4(ah0, ah1, ah2, ah3, ahi_base + kc * 32);
        ldmx4(al0, al1, al2, al3, alo_base + kc * 32);
        #pragma unroll
        for (int nt = 0; nt < 8; nt++) {
            const int idx = ((ntg0 + nt) * 8 + kc) * 32 + lane;
            const uint2 bh = g_wfhi[idx];
            const uint2 bl = g_wflo[idx];
            mma16816(c[nt][0], c[nt][1], c[nt][2], c[nt][3],
                     ah0, ah1, ah2, ah3, bh.x, bh.y);
            mma16816(c[nt][0], c[nt][1], c[nt][2], c[nt][3],
                     al0, al1, al2, al3, bh.x, bh.y);
            mma16816(c[nt][0], c[nt][1], c[nt][2], c[nt][3],
                     ah0, ah1, ah2, ah3, bl.x, bl.y);
        }
    }

    // store (rows gid and gid+8 of this m-tile)
    const int row0 = t0 + mt * 16 + gid;
    const int row1 = row0 + 8;
    #pragma unroll
    for (int nt = 0; nt < 8; nt++) {
        const int col = r0 + (nh * 8 + nt) * 8 + 2 * tig;
        if (row0 < TLEN)
            *reinterpret_cast<float2*>(&g_gi[(b * TLEN + row0) * NR + col]) =
                make_float2(c[nt][0], c[nt][1]);
        if (row1 < TLEN)
            *reinterpret_cast<float2*>(&g_gi[(b * TLEN + row1) * NR + col]) =
                make_float2(c[nt][2], c[nt][3]);
    }
}

// ============================================================================
// Kernel 3: AUGRU scan via tensor cores (unchanged from R6 — validated).
// ============================================================================
#define NWARP 16
#define NTW   3
#define NFRAG (NWARP * 8 * NTW)
#define OFF_BHI  0
#define OFF_BLO  (NFRAG * 32 * 8)
#define OFF_AHI  (OFF_BLO + NFRAG * 32 * 8)
#define OFF_ALO  (OFF_AHI + NB * APITCH * 2)
#define OFF_SG2  (OFF_ALO + NB * APITCH * 2)
#define OFF_ATT  (OFF_SG2 + NB * SG2P * 4)
#define OFF_LEN  (OFF_ATT + NB * 4)
#define REC_SMEM (OFF_LEN + NB * 4)

__global__ void __launch_bounds__(512, 1) rec_kernel(
    const float* __restrict__ Whh, const float* __restrict__ bhh,
    const int* __restrict__ klen, float* __restrict__ out)
{
    extern __shared__ char smc[];
    uint2* sBhi = reinterpret_cast<uint2*>(smc + OFF_BHI);
    uint2* sBlo = reinterpret_cast<uint2*>(smc + OFF_BLO);
    __nv_bfloat16* sAhi = reinterpret_cast<__nv_bfloat16*>(smc + OFF_AHI);
    __nv_bfloat16* sAlo = reinterpret_cast<__nv_bfloat16*>(smc + OFF_ALO);
    float* sg2  = reinterpret_cast<float*>(smc + OFF_SG2);
    float* satt = reinterpret_cast<float*>(smc + OFF_ATT);
    int*   slen = reinterpret_cast<int*>(smc + OFF_LEN);
    __shared__ int smax;

    const int tid  = threadIdx.x;
    const int lane = tid & 31, warp = tid >> 5;
    const int gid  = lane >> 2, tig = lane & 3;
    const int b0   = blockIdx.x * NB;

    #pragma unroll
    for (int kc = 0; kc < 8; kc++) {
        #pragma unroll
        for (int nt = 0; nt < NTW; nt++) {
            const int n = warp * 24 + nt * 8 + gid;
            const float* wr = Whh + n * HD + kc * 16;
            const float w0 = wr[2 * tig],     w1 = wr[2 * tig + 1];
            const float w2 = wr[2 * tig + 8], w3 = wr[2 * tig + 9];
            const __nv_bfloat16 h0 = __float2bfloat16(w0), h1 = __float2bfloat16(w1);
            const __nv_bfloat16 h2 = __float2bfloat16(w2), h3 = __float2bfloat16(w3);
            const int idx = ((warp * 8 + kc) * NTW + nt) * 32 + lane;
            sBhi[idx] = make_uint2(pkbf(w0, w1), pkbf(w2, w3));
            sBlo[idx] = make_uint2(
                pkbf(w0 - __bfloat162float(h0), w1 - __bfloat162float(h1)),
                pkbf(w2 - __bfloat162float(h2), w3 - __bfloat162float(h3)));
        }
    }
    for (int i = tid; i < NB * APITCH; i += 512) {
        sAhi[i] = __float2bfloat16(0.0f);
        sAlo[i] = __float2bfloat16(0.0f);
    }
    if (tid < NB) slen[tid] = klen[b0 + tid];
    __syncthreads();
    if (tid == 0) {
        int m = 0;
        #pragma unroll
        for (int b = 0; b < NB; b++) m = max(m, slen[b]);
        smax = m;
    }
    __syncthreads();
    const int tmax = smax;

    const int lm_m = lane >> 3, lm_r = lane & 7;
    const int lm_row = ((lm_m & 1) ? 8 : 0) + lm_r;
    const int lm_col = (lm_m >> 1) * 8;
    const uint32_t aoff = (uint32_t)((lm_row * APITCH + lm_col) * 2);
    const uint32_t ahi_base = (uint32_t)__cvta_generic_to_shared(sAhi) + aoff;
    const uint32_t alo_base = (uint32_t)__cvta_generic_to_shared(sAlo) + aoff;

    float cb0[NTW], cb1[NTW];
    #pragma unroll
    for (int nt = 0; nt < NTW; nt++) {
        cb0[nt] = bhh[warp * 24 + nt * 8 + 2 * tig];
        cb1[nt] = bhh[warp * 24 + nt * 8 + 2 * tig + 1];
    }

    float hreg[4] = {0.0f, 0.0f, 0.0f, 0.0f};

    for (int t = 0; t < tmax; t++) {
        float pr[4], pz[4], pn[4];
        #pragma unroll
        for (int k = 0; k < 4; k++) {
            const int i = tid + k * 512;
            const int bb = i >> 7, j = i & 127;
            const float* g = &g_gi[((b0 + bb) * TLEN + t) * NR + j];
            pr[k] = g[0];
            pz[k] = g[HD];
            pn[k] = g[2 * HD];
        }
        if (tid < NB) satt[tid] = g_att[(b0 + tid) * TLEN + t];

        float c[NTW][4];
        #pragma unroll
        for (int nt = 0; nt < NTW; nt++) {
            c[nt][0] = cb0[nt]; c[nt][1] = cb1[nt];
            c[nt][2] = cb0[nt]; c[nt][3] = cb1[nt];
        }
        #pragma unroll
        for (int kc = 0; kc < 8; kc++) {
            uint32_t ah0, ah1, ah2, ah3, al0, al1, al2, al3;
            ldmx4(ah0, ah1, ah2, ah3, ahi_base + kc * 32);
            ldmx4(al0, al1, al2, al3, alo_base + kc * 32);
            #pragma unroll
            for (int nt = 0; nt < NTW; nt++) {
                const int idx = ((warp * 8 + kc) * NTW + nt) * 32 + lane;
                const uint2 bh = sBhi[idx];
                const uint2 bl = sBlo[idx];
                mma16816(c[nt][0], c[nt][1], c[nt][2], c[nt][3],
                         ah0, ah1, ah2, ah3, bh.x, bh.y);
                mma16816(c[nt][0], c[nt][1], c[nt][2], c[nt][3],
                         al0, al1, al2, al3, bh.x, bh.y);
                mma16816(c[nt][0], c[nt][1], c[nt][2], c[nt][3],
                         ah0, ah1, ah2, ah3, bl.x, bl.y);
            }
        }
        #pragma unroll
        for (int nt = 0; nt < NTW; nt++) {
            const int colb = warp * 24 + nt * 8 + 2 * tig;
            *reinterpret_cast<float2*>(&sg2[gid * SG2P + colb]) =
                make_float2(c[nt][0], c[nt][1]);
            *reinterpret_cast<float2*>(&sg2[(gid + 8) * SG2P + colb]) =
                make_float2(c[nt][2], c[nt][3]);
        }
        __syncthreads();

        #pragma unroll
        for (int k = 0; k < 4; k++) {
            const int i = tid + k * 512;
            const int bb = i >> 7, j = i & 127;
            if (t < slen[bb]) {
                const float g2r = sg2[bb * SG2P + j];
                const float g2z = sg2[bb * SG2P + HD + j];
                const float g2n = sg2[bb * SG2P + 2 * HD + j];
                const float rr = sigm_t(pr[k] + g2r);
                const float zz = sigm_t(pz[k] + g2z) * satt[bb];
                const float nn = tanh_fast(pn[k] + rr * g2n);
                const float hn = (1.0f - zz) * hreg[k] + zz * nn;
                hreg[k] = hn;
                const __nv_bfloat16 hb = __float2bfloat16(hn);
                sAhi[bb * APITCH + j] = hb;
                sAlo[bb * APITCH + j] = __float2bfloat16(hn - __bfloat162float(hb));
            }
        }
        __syncthreads();
    }

    #pragma unroll
    for (int k = 0; k < 4; k++) {
        const int i = tid + k * 512;
        const int bb = i >> 7, j = i & 127;
        out[(b0 + bb) * HD + j] = (slen[bb] > 0) ? hreg[k] : 0.0f;
    }
}

// ============================================================================
extern "C" void kernel_launch(void* const* d_in, const int* in_sizes, int n_in,
                              void* d_out, int out_size)
{
    const float* query = (const float*)d_in[0];
    const float* keys  = (const float*)d_in[1];
    const float* W0    = (const float*)d_in[2];
    const float* b0    = (const float*)d_in[3];
    const float* W1    = (const float*)d_in[4];
    const float* b1    = (const float*)d_in[5];
    const float* Wd    = (const float*)d_in[6];
    const float* bd    = (const float*)d_in[7];
    const float* Wih   = (const float*)d_in[8];
    const float* Whh   = (const float*)d_in[9];
    const float* bih   = (const float*)d_in[10];
    const float* bhh   = (const float*)d_in[11];
    const int*   klen  = (const int*)d_in[12];
    float* out = (float*)d_out;

    cudaFuncSetAttribute(rec_kernel, cudaFuncAttributeMaxDynamicSharedMemorySize, REC_SMEM);

    wfrag_kernel<<<48, 256>>>(Wih);
    qpart_kernel<<<BATCH / NB, 256>>>(query, W0, b0);
    attn_kernel<<<BATCH, 256>>>(query, keys, W0, W1, b1, Wd, bd, klen);
    gi_kernel<<<dim3(4, 3, BATCH), 256>>>(keys, bih, klen);
    rec_kernel<<<RBLK, 512, REC_SMEM>>>(Whh, bhh, klen, out);
}

// round 8
// speedup vs baseline: 6.0435x; 1.3444x over previous
#include <cuda_runtime.h>
#include <cuda_bf16.h>
#include <cstdint>

#define BATCH 2048
#define TLEN  200
#define HD    128
#define NA0   64
#define NA1   16
#define NB    16
#define RBLK  (BATCH / NB)   // 128 scan blocks
#define NR    384            // 3*HD gate rows
#define SG2P  386            // sg2 pitch (floats), even
#define APITCH 136           // bf16 A pitch: 272B rows -> conflict-free ldmatrix

// ---------------- device scratch (no allocs allowed) ----------------
__device__ float g_att[BATCH * TLEN];            // 1.6 MB attention scores
__device__ float g_qp [BATCH * NA0];             // 0.5 MB qpart
__device__ float g_gi [BATCH * TLEN * NR];       // 629 MB  gi = keys@Wih^T + bih
__device__ uint2 g_wfhi[48 * 8 * 32];            // Wih hi fragments (98KB)
__device__ uint2 g_wflo[48 * 8 * 32];            // Wih lo fragments (98KB)

// ---------------- helpers ----------------
__device__ __forceinline__ unsigned long long ffma2(unsigned long long a,
                                                    unsigned long long b,
                                                    unsigned long long c) {
    unsigned long long d;
    asm("fma.rn.f32x2 %0, %1, %2, %3;" : "=l"(d) : "l"(a), "l"(b), "l"(c));
    return d;
}
__device__ __forceinline__ float2 unpk(unsigned long long v) {
    float2 f;
    asm("mov.b64 {%0, %1}, %2;" : "=f"(f.x), "=f"(f.y) : "l"(v));
    return f;
}
__device__ __forceinline__ float sigm(float x) {
    return __fdividef(1.0f, 1.0f + __expf(-x));
}
__device__ __forceinline__ float tanh_fast(float x) {
    float y;
    asm("tanh.approx.f32 %0, %1;" : "=f"(y) : "f"(x));
    return y;
}
__device__ __forceinline__ float sigm_t(float x) {
    return fmaf(0.5f, tanh_fast(0.5f * x), 0.5f);
}
__device__ __forceinline__ uint32_t pkbf(float lo, float hi) {
    __nv_bfloat16 a = __float2bfloat16(lo), b = __float2bfloat16(hi);
    uint16_t ua = *reinterpret_cast<uint16_t*>(&a);
    uint16_t ub = *reinterpret_cast<uint16_t*>(&b);
    return (uint32_t)ua | ((uint32_t)ub << 16);
}
__device__ __forceinline__ void mma16816(float& c0, float& c1, float& c2, float& c3,
                                         uint32_t a0, uint32_t a1, uint32_t a2, uint32_t a3,
                                         uint32_t b0, uint32_t b1) {
    asm volatile(
        "mma.sync.aligned.m16n8k16.row.col.f32.bf16.bf16.f32 "
        "{%0,%1,%2,%3}, {%4,%5,%6,%7}, {%8,%9}, {%0,%1,%2,%3};"
        : "+f"(c0), "+f"(c1), "+f"(c2), "+f"(c3)
        : "r"(a0), "r"(a1), "r"(a2), "r"(a3), "r"(b0), "r"(b1));
}
__device__ __forceinline__ void ldmx4(uint32_t& r0, uint32_t& r1, uint32_t& r2, uint32_t& r3,
                                      uint32_t addr) {
    asm volatile("ldmatrix.sync.aligned.m8n8.x4.shared.b16 {%0,%1,%2,%3}, [%4];"
                 : "=r"(r0), "=r"(r1), "=r"(r2), "=r"(r3) : "r"(addr));
}

// ============================================================================
// Kernel W: build Wih bf16 hi/lo fragments in global (once).
// ============================================================================
__global__ void __launch_bounds__(256) wfrag_kernel(const float* __restrict__ Wih)
{
    const int nt   = blockIdx.x;
    const int tid  = threadIdx.x;
    const int kc   = tid >> 5;
    const int lane = tid & 31;
    const int gid  = lane >> 2, tig = lane & 3;

    const int n = nt * 8 + gid;
    const float* wr = Wih + n * HD + kc * 16;
    const float w0 = wr[2 * tig],     w1 = wr[2 * tig + 1];
    const float w2 = wr[2 * tig + 8], w3 = wr[2 * tig + 9];
    const __nv_bfloat16 h0 = __float2bfloat16(w0), h1 = __float2bfloat16(w1);
    const __nv_bfloat16 h2 = __float2bfloat16(w2), h3 = __float2bfloat16(w3);
    const int idx = (nt * 8 + kc) * 32 + lane;
    g_wfhi[idx] = make_uint2(pkbf(w0, w1), pkbf(w2, w3));
    g_wflo[idx] = make_uint2(
        pkbf(w0 - __bfloat162float(h0), w1 - __bfloat162float(h1)),
        pkbf(w2 - __bfloat162float(h2), w3 - __bfloat162float(h3)));
}

// ============================================================================
// Kernel 0: qpart[b][o] = b0[o] + sum_j (W0a[o,j]+W0c[o,j]) * q[b][j]
// ============================================================================
__global__ void __launch_bounds__(256) qpart_kernel(
    const float* __restrict__ query, const float* __restrict__ W0,
    const float* __restrict__ b0)
{
    __shared__ float sWeff[NA0 * 132];
    __shared__ float sqq[NB * HD];

    const int tid = threadIdx.x;
    const int b0i = blockIdx.x * NB;

    for (int idx = tid; idx < NA0 * HD; idx += 256) {
        const int o = idx >> 7, j = idx & 127;
        sWeff[o * 132 + j] = W0[o * (4 * HD) + j] + W0[o * (4 * HD) + 2 * HD + j];
    }
    for (int idx = tid; idx < NB * HD; idx += 256)
        sqq[idx] = query[b0i * HD + idx];
    __syncthreads();

    const int o  = tid & 63;
    const int bg = tid >> 6;
    unsigned long long acc[4];
    #pragma unroll
    for (int i = 0; i < 4; i++) acc[i] = 0ull;

    #pragma unroll 4
    for (int jc = 0; jc < HD / 4; jc++) {
        const ulonglong2 w = *reinterpret_cast<const ulonglong2*>(&sWeff[o * 132 + jc * 4]);
        #pragma unroll
        for (int i = 0; i < 4; i++) {
            const ulonglong2 x =
                *reinterpret_cast<const ulonglong2*>(&sqq[(bg * 4 + i) * HD + jc * 4]);
            acc[i] = ffma2(w.x, x.x, acc[i]);
            acc[i] = ffma2(w.y, x.y, acc[i]);
        }
    }
    const float bo = b0[o];
    #pragma unroll
    for (int i = 0; i < 4; i++) {
        const float2 p = unpk(acc[i]);
        g_qp[(b0i + bg * 4 + i) * NA0 + o] = p.x + p.y + bo;
    }
}

// ============================================================================
// Kernel 1: DIN attention via tensor cores.  One block per batch, 256 thr.
// Layer0: [64t x 64n x 128k] MMA per chunk (3-term bf16 split), B = per-batch
// effective weights Wk (built from W0 and q into fragments).  Layer1 + score
// scalar with 4-lane shuffle reduction.
// ============================================================================
// dynamic smem offsets (bytes)
#define OFFA_BHI 0
#define OFFA_BLO (OFFA_BHI + 8 * 8 * 32 * 8)        // 16384
#define OFFA_AHI (OFFA_BLO + 8 * 8 * 32 * 8)        // 32768
#define OFFA_ALO (OFFA_AHI + 64 * APITCH * 2)       // 50176
#define OFFA_SA0 (OFFA_ALO + 64 * APITCH * 2)       // 67584
#define OFFA_W1  (OFFA_SA0 + 64 * 68 * 4)           // 84992
#define OFFA_SQ  (OFFA_W1 + NA1 * 65 * 4)           // 89152
#define OFFA_QP  (OFFA_SQ + HD * 4)                 // 89664
#define OFFA_WD  (OFFA_QP + NA0 * 4)                // 89920
#define OFFA_B1  (OFFA_WD + NA1 * 4)                // 89984
#define ATTN_SMEM (OFFA_B1 + NA1 * 4)               // 90048

__global__ void __launch_bounds__(256) attn_kernel(
    const float* __restrict__ query, const float* __restrict__ keys,
    const float* __restrict__ W0,
    const float* __restrict__ W1, const float* __restrict__ b1,
    const float* __restrict__ Wd, const float* __restrict__ bd,
    const int* __restrict__ klen)
{
    extern __shared__ char smc[];
    uint2* sBhi = reinterpret_cast<uint2*>(smc + OFFA_BHI);
    uint2* sBlo = reinterpret_cast<uint2*>(smc + OFFA_BLO);
    __nv_bfloat16* sAhi = reinterpret_cast<__nv_bfloat16*>(smc + OFFA_AHI);
    __nv_bfloat16* sAlo = reinterpret_cast<__nv_bfloat16*>(smc + OFFA_ALO);
    float* sa0 = reinterpret_cast<float*>(smc + OFFA_SA0);
    float* sW1 = reinterpret_cast<float*>(smc + OFFA_W1);
    float* sq  = reinterpret_cast<float*>(smc + OFFA_SQ);
    float* sqp = reinterpret_cast<float*>(smc + OFFA_QP);
    float* sWd = reinterpret_cast<float*>(smc + OFFA_WD);
    float* sb1 = reinterpret_cast<float*>(smc + OFFA_B1);

    const int b    = blockIdx.x;
    const int tid  = threadIdx.x;
    const int lenb = klen[b];
    const int lane = tid & 31, warp = tid >> 5;
    const int gid  = lane >> 2, tig = lane & 3;

    if (tid < HD) sq[tid] = query[b * HD + tid];
    if (tid < NA0) sqp[tid] = g_qp[b * NA0 + tid];
    if (tid < NA1) { sWd[tid] = Wd[tid]; sb1[tid] = b1[tid]; }
    for (int i = tid; i < NA1 * NA0; i += 256) {
        const int p = i >> 6, o = i & 63;
        sW1[p * 65 + o] = W1[i];
    }
    const float bd0 = bd[0];
    __syncthreads();

    // ---- build per-batch Wk fragments (warp = kc) ----
    {
        const int kc = warp;
        #pragma unroll
        for (int nt = 0; nt < 8; nt++) {
            const int n = nt * 8 + gid;
            const float* wr = W0 + n * (4 * HD);
            const int j0 = kc * 16 + 2 * tig;
            const int j2 = j0 + 8;
            const float w0 = wr[HD + j0]     - wr[2 * HD + j0]     + wr[3 * HD + j0]     * sq[j0];
            const float w1 = wr[HD + j0 + 1] - wr[2 * HD + j0 + 1] + wr[3 * HD + j0 + 1] * sq[j0 + 1];
            const float w2 = wr[HD + j2]     - wr[2 * HD + j2]     + wr[3 * HD + j2]     * sq[j2];
            const float w3 = wr[HD + j2 + 1] - wr[2 * HD + j2 + 1] + wr[3 * HD + j2 + 1] * sq[j2 + 1];
            const __nv_bfloat16 h0 = __float2bfloat16(w0), h1 = __float2bfloat16(w1);
            const __nv_bfloat16 h2 = __float2bfloat16(w2), h3 = __float2bfloat16(w3);
            const int idx = (kc * 8 + nt) * 32 + lane;
            sBhi[idx] = make_uint2(pkbf(w0, w1), pkbf(w2, w3));
            sBlo[idx] = make_uint2(
                pkbf(w0 - __bfloat162float(h0), w1 - __bfloat162float(h1)),
                pkbf(w2 - __bfloat162float(h2), w3 - __bfloat162float(h3)));
        }
    }
    __syncthreads();

    const int mt = warp & 3;          // m-tile within chunk
    const int nh = warp >> 2;         // n-half (4 n-tiles each)
    const int lm_m = lane >> 3, lm_r = lane & 7;
    const int lm_row = mt * 16 + ((lm_m & 1) ? 8 : 0) + lm_r;
    const int lm_col = (lm_m >> 1) * 8;
    const uint32_t aoff = (uint32_t)((lm_row * APITCH + lm_col) * 2);
    const uint32_t ahi_base = (uint32_t)__cvta_generic_to_shared(sAhi) + aoff;
    const uint32_t alo_base = (uint32_t)__cvta_generic_to_shared(sAlo) + aoff;

    for (int t0c = 0; t0c < TLEN; t0c += 64) {
        if (t0c >= lenb) {      // block-uniform: zero-fill scores
            for (int i = tid; i < 64; i += 256) {
                const int tg = t0c + i;
                if (tg < TLEN) g_att[b * TLEN + tg] = 0.0f;
            }
            continue;
        }
        // stage keys chunk -> bf16 hi/lo
        for (int idx = tid; idx < 64 * HD; idx += 256) {
            const int tt = idx >> 7, j = idx & 127;
            const int tg = t0c + tt;
            const float v = (tg < TLEN) ? keys[(b * TLEN + tg) * HD + j] : 0.0f;
            const __nv_bfloat16 h = __float2bfloat16(v);
            sAhi[tt * APITCH + j] = h;
            sAlo[tt * APITCH + j] = __float2bfloat16(v - __bfloat162float(h));
        }
        __syncthreads();

        // layer0 MMA (accumulators seeded with qpart)
        float c[4][4];
        #pragma unroll
        for (int nt = 0; nt < 4; nt++) {
            const int col = (nh * 4 + nt) * 8 + 2 * tig;
            c[nt][0] = sqp[col]; c[nt][1] = sqp[col + 1];
            c[nt][2] = sqp[col]; c[nt][3] = sqp[col + 1];
        }
        #pragma unroll
        for (int kc = 0; kc < 8; kc++) {
            uint32_t ah0, ah1, ah2, ah3, al0, al1, al2, al3;
            ldmx4(ah0, ah1, ah2, ah3, ahi_base + kc * 32);
            ldmx4(al0, al1, al2, al3, alo_base + kc * 32);
            #pragma unroll
            for (int nt = 0; nt < 4; nt++) {
                const int idx = (kc * 8 + nh * 4 + nt) * 32 + lane;
                const uint2 bh = sBhi[idx];
                const uint2 bl = sBlo[idx];
                mma16816(c[nt][0], c[nt][1], c[nt][2], c[nt][3],
                         ah0, ah1, ah2, ah3, bh.x, bh.y);
                mma16816(c[nt][0], c[nt][1], c[nt][2], c[nt][3],
                         al0, al1, al2, al3, bh.x, bh.y);
                mma16816(c[nt][0], c[nt][1], c[nt][2], c[nt][3],
                         ah0, ah1, ah2, ah3, bl.x, bl.y);
            }
        }
        // sigmoid -> sa0
        const int row0 = mt * 16 + gid;
        #pragma unroll
        for (int nt = 0; nt < 4; nt++) {
            const int col = (nh * 4 + nt) * 8 + 2 * tig;
            sa0[row0 * 68 + col]           = sigm(c[nt][0]);
            sa0[row0 * 68 + col + 1]       = sigm(c[nt][1]);
            sa0[(row0 + 8) * 68 + col]     = sigm(c[nt][2]);
            sa0[(row0 + 8) * 68 + col + 1] = sigm(c[nt][3]);
        }
        __syncthreads();

        // layer1 + score: 4 lanes per row, each 4 p-values
        {
            const int row = tid >> 2, sub = tid & 3;
            float s0 = sb1[sub * 4], s1 = sb1[sub * 4 + 1];
            float s2 = sb1[sub * 4 + 2], s3 = sb1[sub * 4 + 3];
            const float* w1r = &sW1[(sub * 4) * 65];
            #pragma unroll 8
            for (int o = 0; o < NA0; o++) {
                const float a = sa0[row * 68 + o];
                s0 = fmaf(w1r[o], a, s0);
                s1 = fmaf(w1r[65 + o], a, s1);
                s2 = fmaf(w1r[130 + o], a, s2);
                s3 = fmaf(w1r[195 + o], a, s3);
            }
            float part = sWd[sub * 4] * sigm(s0) + sWd[sub * 4 + 1] * sigm(s1)
                       + sWd[sub * 4 + 2] * sigm(s2) + sWd[sub * 4 + 3] * sigm(s3);
            part += __shfl_xor_sync(0xffffffffu, part, 1);
            part += __shfl_xor_sync(0xffffffffu, part, 2);
            if (sub == 0) {
                const int tg = t0c + row;
                if (tg < TLEN)
                    g_att[b * TLEN + tg] = (tg < lenb) ? part + bd0 : 0.0f;
            }
        }
        __syncthreads();
    }
}

// ============================================================================
// Kernel 2: gi GEMM via tensor cores (unchanged from R7 — validated).
// ============================================================================
__global__ void __launch_bounds__(256) gi_kernel(
    const float* __restrict__ keys, const float* __restrict__ bih,
    const int* __restrict__ klen)
{
    __shared__ __nv_bfloat16 sAhi[64 * APITCH];
    __shared__ __nv_bfloat16 sAlo[64 * APITCH];

    const int b    = blockIdx.z;
    const int t0   = blockIdx.x * 64;
    const int r0   = blockIdx.y * 128;
    const int lenb = klen[b];
    if (t0 >= lenb) return;

    const int tid = threadIdx.x;

    for (int idx = tid; idx < 64 * HD; idx += 256) {
        const int tt = idx >> 7, j = idx & 127;
        const int tg = t0 + tt;
        const float v = (tg < TLEN) ? keys[(b * TLEN + tg) * HD + j] : 0.0f;
        const __nv_bfloat16 h = __float2bfloat16(v);
        sAhi[tt * APITCH + j] = h;
        sAlo[tt * APITCH + j] = __float2bfloat16(v - __bfloat162float(h));
    }
    __syncthreads();

    const int lane = tid & 31, warp = tid >> 5;
    const int gid  = lane >> 2, tig = lane & 3;
    const int mt   = warp & 3;
    const int nh   = warp >> 2;

    const int lm_m = lane >> 3, lm_r = lane & 7;
    const int lm_row = mt * 16 + ((lm_m & 1) ? 8 : 0) + lm_r;
    const int lm_col = (lm_m >> 1) * 8;
    const uint32_t aoff = (uint32_t)((lm_row * APITCH + lm_col) * 2);
    const uint32_t ahi_base = (uint32_t)__cvta_generic_to_shared(sAhi) + aoff;
    const uint32_t alo_base = (uint32_t)__cvta_generic_to_shared(sAlo) + aoff;

    float c[8][4];
    #pragma unroll
    for (int nt = 0; nt < 8; nt++) {
        const int col = r0 + (nh * 8 + nt) * 8 + 2 * tig;
        const float bv0 = bih[col], bv1 = bih[col + 1];
        c[nt][0] = bv0; c[nt][1] = bv1; c[nt][2] = bv0; c[nt][3] = bv1;
    }

    const int ntg0 = (r0 >> 3) + nh * 8;

    #pragma unroll
    for (int kc = 0; kc < 8; kc++) {
        uint32_t ah0, ah1, ah2, ah3, al0, al1, al2, al3;
        ldmx4(ah0, ah1, ah2, ah3, ahi_base + kc * 32);
        ldmx4(al0, al1, al2, al3, alo_base + kc * 32);
        #pragma unroll
        for (int nt = 0; nt < 8; nt++) {
            const int idx = ((ntg0 + nt) * 8 + kc) * 32 + lane;
            const uint2 bh = g_wfhi[idx];
            const uint2 bl = g_wflo[idx];
            mma16816(c[nt][0], c[nt][1], c[nt][2], c[nt][3],
                     ah0, ah1, ah2, ah3, bh.x, bh.y);
            mma16816(c[nt][0], c[nt][1], c[nt][2], c[nt][3],
                     al0, al1, al2, al3, bh.x, bh.y);
            mma16816(c[nt][0], c[nt][1], c[nt][2], c[nt][3],
                     ah0, ah1, ah2, ah3, bl.x, bl.y);
        }
    }

    const int row0 = t0 + mt * 16 + gid;
    const int row1 = row0 + 8;
    #pragma unroll
    for (int nt = 0; nt < 8; nt++) {
        const int col = r0 + (nh * 8 + nt) * 8 + 2 * tig;
        if (row0 < TLEN)
            *reinterpret_cast<float2*>(&g_gi[(b * TLEN + row0) * NR + col]) =
                make_float2(c[nt][0], c[nt][1]);
        if (row1 < TLEN)
            *reinterpret_cast<float2*>(&g_gi[(b * TLEN + row1) * NR + col]) =
                make_float2(c[nt][2], c[nt][3]);
    }
}

// ============================================================================
// Kernel 3: AUGRU scan via tensor cores (unchanged from R6 — validated).
// ============================================================================
#define NWARP 16
#define NTW   3
#define NFRAG (NWARP * 8 * NTW)
#define OFF_BHI  0
#define OFF_BLO  (NFRAG * 32 * 8)
#define OFF_AHI  (OFF_BLO + NFRAG * 32 * 8)
#define OFF_ALO  (OFF_AHI + NB * APITCH * 2)
#define OFF_SG2  (OFF_ALO + NB * APITCH * 2)
#define OFF_ATT  (OFF_SG2 + NB * SG2P * 4)
#define OFF_LEN  (OFF_ATT + NB * 4)
#define REC_SMEM (OFF_LEN + NB * 4)

__global__ void __launch_bounds__(512, 1) rec_kernel(
    const float* __restrict__ Whh, const float* __restrict__ bhh,
    const int* __restrict__ klen, float* __restrict__ out)
{
    extern __shared__ char smc[];
    uint2* sBhi = reinterpret_cast<uint2*>(smc + OFF_BHI);
    uint2* sBlo = reinterpret_cast<uint2*>(smc + OFF_BLO);
    __nv_bfloat16* sAhi = reinterpret_cast<__nv_bfloat16*>(smc + OFF_AHI);
    __nv_bfloat16* sAlo = reinterpret_cast<__nv_bfloat16*>(smc + OFF_ALO);
    float* sg2  = reinterpret_cast<float*>(smc + OFF_SG2);
    float* satt = reinterpret_cast<float*>(smc + OFF_ATT);
    int*   slen = reinterpret_cast<int*>(smc + OFF_LEN);
    __shared__ int smax;

    const int tid  = threadIdx.x;
    const int lane = tid & 31, warp = tid >> 5;
    const int gid  = lane >> 2, tig = lane & 3;
    const int b0   = blockIdx.x * NB;

    #pragma unroll
    for (int kc = 0; kc < 8; kc++) {
        #pragma unroll
        for (int nt = 0; nt < NTW; nt++) {
            const int n = warp * 24 + nt * 8 + gid;
            const float* wr = Whh + n * HD + kc * 16;
            const float w0 = wr[2 * tig],     w1 = wr[2 * tig + 1];
            const float w2 = wr[2 * tig + 8], w3 = wr[2 * tig + 9];
            const __nv_bfloat16 h0 = __float2bfloat16(w0), h1 = __float2bfloat16(w1);
            const __nv_bfloat16 h2 = __float2bfloat16(w2), h3 = __float2bfloat16(w3);
            const int idx = ((warp * 8 + kc) * NTW + nt) * 32 + lane;
            sBhi[idx] = make_uint2(pkbf(w0, w1), pkbf(w2, w3));
            sBlo[idx] = make_uint2(
                pkbf(w0 - __bfloat162float(h0), w1 - __bfloat162float(h1)),
                pkbf(w2 - __bfloat162float(h2), w3 - __bfloat162float(h3)));
        }
    }
    for (int i = tid; i < NB * APITCH; i += 512) {
        sAhi[i] = __float2bfloat16(0.0f);
        sAlo[i] = __float2bfloat16(0.0f);
    }
    if (tid < NB) slen[tid] = klen[b0 + tid];
    __syncthreads();
    if (tid == 0) {
        int m = 0;
        #pragma unroll
        for (int b = 0; b < NB; b++) m = max(m, slen[b]);
        smax = m;
    }
    __syncthreads();
    const int tmax = smax;

    const int lm_m = lane >> 3, lm_r = lane & 7;
    const int lm_row = ((lm_m & 1) ? 8 : 0) + lm_r;
    const int lm_col = (lm_m >> 1) * 8;
    const uint32_t aoff = (uint32_t)((lm_row * APITCH + lm_col) * 2);
    const uint32_t ahi_base = (uint32_t)__cvta_generic_to_shared(sAhi) + aoff;
    const uint32_t alo_base = (uint32_t)__cvta_generic_to_shared(sAlo) + aoff;

    float cb0[NTW], cb1[NTW];
    #pragma unroll
    for (int nt = 0; nt < NTW; nt++) {
        cb0[nt] = bhh[warp * 24 + nt * 8 + 2 * tig];
        cb1[nt] = bhh[warp * 24 + nt * 8 + 2 * tig + 1];
    }

    float hreg[4] = {0.0f, 0.0f, 0.0f, 0.0f};

    for (int t = 0; t < tmax; t++) {
        float pr[4], pz[4], pn[4];
        #pragma unroll
        for (int k = 0; k < 4; k++) {
            const int i = tid + k * 512;
            const int bb = i >> 7, j = i & 127;
            const float* g = &g_gi[((b0 + bb) * TLEN + t) * NR + j];
            pr[k] = g[0];
            pz[k] = g[HD];
            pn[k] = g[2 * HD];
        }
        if (tid < NB) satt[tid] = g_att[(b0 + tid) * TLEN + t];

        float c[NTW][4];
        #pragma unroll
        for (int nt = 0; nt < NTW; nt++) {
            c[nt][0] = cb0[nt]; c[nt][1] = cb1[nt];
            c[nt][2] = cb0[nt]; c[nt][3] = cb1[nt];
        }
        #pragma unroll
        for (int kc = 0; kc < 8; kc++) {
            uint32_t ah0, ah1, ah2, ah3, al0, al1, al2, al3;
            ldmx4(ah0, ah1, ah2, ah3, ahi_base + kc * 32);
            ldmx4(al0, al1, al2, al3, alo_base + kc * 32);
            #pragma unroll
            for (int nt = 0; nt < NTW; nt++) {
                const int idx = ((warp * 8 + kc) * NTW + nt) * 32 + lane;
                const uint2 bh = sBhi[idx];
                const uint2 bl = sBlo[idx];
                mma16816(c[nt][0], c[nt][1], c[nt][2], c[nt][3],
                         ah0, ah1, ah2, ah3, bh.x, bh.y);
                mma16816(c[nt][0], c[nt][1], c[nt][2], c[nt][3],
                         al0, al1, al2, al3, bh.x, bh.y);
                mma16816(c[nt][0], c[nt][1], c[nt][2], c[nt][3],
                         ah0, ah1, ah2, ah3, bl.x, bl.y);
            }
        }
        #pragma unroll
        for (int nt = 0; nt < NTW; nt++) {
            const int colb = warp * 24 + nt * 8 + 2 * tig;
            *reinterpret_cast<float2*>(&sg2[gid * SG2P + colb]) =
                make_float2(c[nt][0], c[nt][1]);
            *reinterpret_cast<float2*>(&sg2[(gid + 8) * SG2P + colb]) =
                make_float2(c[nt][2], c[nt][3]);
        }
        __syncthreads();

        #pragma unroll
        for (int k = 0; k < 4; k++) {
            const int i = tid + k * 512;
            const int bb = i >> 7, j = i & 127;
            if (t < slen[bb]) {
                const float g2r = sg2[bb * SG2P + j];
                const float g2z = sg2[bb * SG2P + HD + j];
                const float g2n = sg2[bb * SG2P + 2 * HD + j];
                const float rr = sigm_t(pr[k] + g2r);
                const float zz = sigm_t(pz[k] + g2z) * satt[bb];
                const float nn = tanh_fast(pn[k] + rr * g2n);
                const float hn = (1.0f - zz) * hreg[k] + zz * nn;
                hreg[k] = hn;
                const __nv_bfloat16 hb = __float2bfloat16(hn);
                sAhi[bb * APITCH + j] = hb;
                sAlo[bb * APITCH + j] = __float2bfloat16(hn - __bfloat162float(hb));
            }
        }
        __syncthreads();
    }

    #pragma unroll
    for (int k = 0; k < 4; k++) {
        const int i = tid + k * 512;
        const int bb = i >> 7, j = i & 127;
        out[(b0 + bb) * HD + j] = (slen[bb] > 0) ? hreg[k] : 0.0f;
    }
}

// ============================================================================
extern "C" void kernel_launch(void* const* d_in, const int* in_sizes, int n_in,
                              void* d_out, int out_size)
{
    const float* query = (const float*)d_in[0];
    const float* keys  = (const float*)d_in[1];
    const float* W0    = (const float*)d_in[2];
    const float* b0    = (const float*)d_in[3];
    const float* W1    = (const float*)d_in[4];
    const float* b1    = (const float*)d_in[5];
    const float* Wd    = (const float*)d_in[6];
    const float* bd    = (const float*)d_in[7];
    const float* Wih   = (const float*)d_in[8];
    const float* Whh   = (const float*)d_in[9];
    const float* bih   = (const float*)d_in[10];
    const float* bhh   = (const float*)d_in[11];
    const int*   klen  = (const int*)d_in[12];
    float* out = (float*)d_out;

    cudaFuncSetAttribute(attn_kernel, cudaFuncAttributeMaxDynamicSharedMemorySize, ATTN_SMEM);
    cudaFuncSetAttribute(rec_kernel,  cudaFuncAttributeMaxDynamicSharedMemorySize, REC_SMEM);

    wfrag_kernel<<<48, 256>>>(Wih);
    qpart_kernel<<<BATCH / NB, 256>>>(query, W0, b0);
    attn_kernel<<<BATCH, 256, ATTN_SMEM>>>(query, keys, W0, W1, b1, Wd, bd, klen);
    gi_kernel<<<dim3(4, 3, BATCH), 256>>>(keys, bih, klen);
    rec_kernel<<<RBLK, 512, REC_SMEM>>>(Whh, bhh, klen, out);
}